// round 2
// baseline (speedup 1.0000x reference)
#include <cuda_runtime.h>
#include <math.h>

// ---------------------------------------------------------------------------
// GNN over a fixed 4-node graph, batch B=32768.
//   build 4x4 mixing matrices (GCN normalized adjacency, SAGE mean matrix)
//   L1: premix(x, A)     -> SGEMM K=64   -> +b1, relu        -> bufA [B,4,1024]
//   L2: premix(bufA, M)  -> SGEMM K=2048 (concat Wl|Wr) +bl  -> bufC [B,4,512]; l2norm+relu
//   L3: premix(bufC, M)  -> SGEMM K=1024 (concat)       +bl  -> bufA [B,4,256]; l2norm+relu
//   L4: premix(bufA, M)  -> SGEMM K=512  (concat)       +bl  -> bufC [B,4,256]; l2norm+relu
//   FC: [B,1024] @ Wfc[1024,10] + bfc -> softmax -> d_out
// ---------------------------------------------------------------------------

#define MAXB 32768

__device__ float g_A[16];   // GCN: out[n] = sum_m g_A[n*4+m] * x[m]
__device__ float g_M[16];   // SAGE mean aggregation matrix
__device__ float g_bufA[(size_t)MAXB * 4 * 1024];
__device__ float g_bufB[(size_t)MAXB * 4 * 1024];
__device__ float g_bufC[(size_t)MAXB * 4 * 1024];

// ---------------------------------------------------------------------------
// Build the two 4x4 mixing matrices from edge_index ([2, E]).
// Dtype-adaptive: JAX may emit int32 (x64 disabled) or int64. Probe the first
// E entries as int64 (in-bounds for both layouts); if any value is outside
// [0,4), the data is int32.
// ---------------------------------------------------------------------------
__global__ void build_graph_kernel(const void* __restrict__ ei_raw, int E)
{
    if (threadIdx.x != 0 || blockIdx.x != 0) return;

    const long long* e64 = (const long long*)ei_raw;
    const int*       e32 = (const int*)ei_raw;

    bool is64 = true;
    for (int e = 0; e < E; ++e) {
        long long v = e64[e];
        if (v < 0 || v >= 4) { is64 = false; break; }
    }

    int src[64], dst[64];   // E <= 64 assumed (E=12 here)
    for (int e = 0; e < E; ++e) {
        if (is64) { src[e] = (int)e64[e]; dst[e] = (int)e64[E + e]; }
        else      { src[e] = e32[e];      dst[e] = e32[E + e]; }
    }

    float degG[4] = {1.f, 1.f, 1.f, 1.f};   // GCN in-degree incl. self loop
    float cntS[4] = {0.f, 0.f, 0.f, 0.f};   // SAGE in-degree (no self loop)
    for (int e = 0; e < E; ++e) {
        degG[dst[e]] += 1.f;
        cntS[dst[e]] += 1.f;
    }
    float dinv[4];
    #pragma unroll
    for (int n = 0; n < 4; ++n) dinv[n] = rsqrtf(degG[n]);

    float A[16], M[16];
    #pragma unroll
    for (int i = 0; i < 16; ++i) { A[i] = 0.f; M[i] = 0.f; }
    for (int e = 0; e < E; ++e) {
        int s = src[e], d = dst[e];
        A[d * 4 + s] += dinv[s] * dinv[d];
        M[d * 4 + s] += 1.f / fmaxf(cntS[d], 1.f);
    }
    #pragma unroll
    for (int n = 0; n < 4; ++n) A[n * 4 + n] += dinv[n] * dinv[n];
    #pragma unroll
    for (int i = 0; i < 16; ++i) { g_A[i] = A[i]; g_M[i] = M[i]; }
}

// ---------------------------------------------------------------------------
// Premix: Y[b,n,f] = sum_m mat[n,m] * X[b,m,f].  which: 0 -> g_A, 1 -> g_M.
// One thread per (b, f/4), float4 vectorized.
// ---------------------------------------------------------------------------
__global__ void premix_kernel(const float* __restrict__ X, float* __restrict__ Y,
                              int B, int F, int which)
{
    const float* mat = which ? g_M : g_A;
    int f4cnt = F >> 2;
    long long idx = (long long)blockIdx.x * blockDim.x + threadIdx.x;
    if (idx >= (long long)B * f4cnt) return;
    int f4 = (int)(idx % f4cnt);
    long long b = idx / f4cnt;

    const float4* Xb = reinterpret_cast<const float4*>(X) + b * 4 * f4cnt;
    float4*       Yb = reinterpret_cast<float4*>(Y)       + b * 4 * f4cnt;

    float4 xv[4];
    #pragma unroll
    for (int m = 0; m < 4; ++m) xv[m] = Xb[(size_t)m * f4cnt + f4];

    #pragma unroll
    for (int n = 0; n < 4; ++n) {
        float m0 = mat[n * 4 + 0], m1 = mat[n * 4 + 1];
        float m2 = mat[n * 4 + 2], m3 = mat[n * 4 + 3];
        float4 r;
        r.x = m0 * xv[0].x + m1 * xv[1].x + m2 * xv[2].x + m3 * xv[3].x;
        r.y = m0 * xv[0].y + m1 * xv[1].y + m2 * xv[2].y + m3 * xv[3].y;
        r.z = m0 * xv[0].z + m1 * xv[1].z + m2 * xv[2].z + m3 * xv[3].z;
        r.w = m0 * xv[0].w + m1 * xv[1].w + m2 * xv[2].w + m3 * xv[3].w;
        Yb[(size_t)n * f4cnt + f4] = r;
    }
}

// ---------------------------------------------------------------------------
// SGEMM: C[M,N] = concat(A0,A1)[M, K0*nparts] @ concat(W0,W1)[K0*nparts, N] + bias
// A parts are [M,K0] row-major; W parts are [K0,N] row-major.
// BM=BN=128, BK=8, 256 threads, 8x8 per thread. M%128==0, N%128==0, K0%8==0.
// ---------------------------------------------------------------------------
__global__ __launch_bounds__(256)
void sgemm_kernel(const float* __restrict__ A0, const float* __restrict__ A1,
                  const float* __restrict__ W0, const float* __restrict__ W1p,
                  const float* __restrict__ bias, float* __restrict__ C,
                  int M, int N, int K0, int nparts, int relu)
{
    __shared__ __align__(16) float As[8][128];
    __shared__ __align__(16) float Ws[8][128];

    const int tid  = threadIdx.x;
    const int bn   = blockIdx.x;
    const int bm   = blockIdx.y;
    const long long row0 = (long long)bm * 128;
    const int col0 = bn * 128;
    const int K = K0 * nparts;

    const int tx = tid & 15;         // 0..15 -> N sub-tile
    const int ty = tid >> 4;         // 0..15 -> M sub-tile

    const int arow = tid >> 1;       // 0..127
    const int acol = (tid & 1) * 4;  // 0 or 4
    const int wrow = tid >> 5;       // 0..7
    const int wcol = (tid & 31) * 4; // 0..124

    float acc[8][8];
    #pragma unroll
    for (int i = 0; i < 8; ++i)
        #pragma unroll
        for (int j = 0; j < 8; ++j) acc[i][j] = 0.f;

    for (int k0 = 0; k0 < K; k0 += 8) {
        const float* Ap;
        const float* Wp;
        int kk;
        if (k0 < K0) { Ap = A0; Wp = W0;  kk = k0; }
        else         { Ap = A1; Wp = W1p; kk = k0 - K0; }

        float4 av = *reinterpret_cast<const float4*>(
            Ap + (size_t)(row0 + arow) * K0 + kk + acol);
        As[acol + 0][arow] = av.x;
        As[acol + 1][arow] = av.y;
        As[acol + 2][arow] = av.z;
        As[acol + 3][arow] = av.w;

        float4 wv = *reinterpret_cast<const float4*>(
            Wp + (size_t)(kk + wrow) * N + col0 + wcol);
        *reinterpret_cast<float4*>(&Ws[wrow][wcol]) = wv;

        __syncthreads();

        #pragma unroll
        for (int k = 0; k < 8; ++k) {
            float a[8], b[8];
            #pragma unroll
            for (int i = 0; i < 8; ++i) a[i] = As[k][ty * 8 + i];
            #pragma unroll
            for (int j = 0; j < 8; ++j) b[j] = Ws[k][tx * 8 + j];
            #pragma unroll
            for (int i = 0; i < 8; ++i)
                #pragma unroll
                for (int j = 0; j < 8; ++j)
                    acc[i][j] += a[i] * b[j];
        }
        __syncthreads();
    }

    // epilogue: + bias, optional relu, float4 stores
    #pragma unroll
    for (int i = 0; i < 8; ++i) {
        long long r = row0 + ty * 8 + i;
        float* crow = C + (size_t)r * N + col0 + tx * 8;
        #pragma unroll
        for (int j4 = 0; j4 < 2; ++j4) {
            float4 v;
            int c0 = col0 + tx * 8 + j4 * 4;
            v.x = acc[i][j4 * 4 + 0] + bias[c0 + 0];
            v.y = acc[i][j4 * 4 + 1] + bias[c0 + 1];
            v.z = acc[i][j4 * 4 + 2] + bias[c0 + 2];
            v.w = acc[i][j4 * 4 + 3] + bias[c0 + 3];
            if (relu) {
                v.x = fmaxf(v.x, 0.f); v.y = fmaxf(v.y, 0.f);
                v.z = fmaxf(v.z, 0.f); v.w = fmaxf(v.w, 0.f);
            }
            *reinterpret_cast<float4*>(crow + j4 * 4) = v;
        }
    }
}

// ---------------------------------------------------------------------------
// Row-wise L2 normalize (max(||row||,1e-12)) then relu, in place.
// One warp per row; N in {256, 512}, N % 128 == 0.
// ---------------------------------------------------------------------------
__global__ void norm_relu_kernel(float* __restrict__ H, long long rows, int N)
{
    long long warp = ((long long)blockIdx.x * blockDim.x + threadIdx.x) >> 5;
    int lane = threadIdx.x & 31;
    if (warp >= rows) return;
    float* h = H + (size_t)warp * N;

    float ss = 0.f;
    for (int k = lane * 4; k < N; k += 128) {
        float4 v = *reinterpret_cast<const float4*>(h + k);
        ss += v.x * v.x + v.y * v.y + v.z * v.z + v.w * v.w;
    }
    #pragma unroll
    for (int off = 16; off > 0; off >>= 1)
        ss += __shfl_xor_sync(0xffffffffu, ss, off);

    float inv = 1.f / fmaxf(sqrtf(ss), 1e-12f);

    for (int k = lane * 4; k < N; k += 128) {
        float4 v = *reinterpret_cast<const float4*>(h + k);
        v.x = fmaxf(v.x * inv, 0.f);
        v.y = fmaxf(v.y * inv, 0.f);
        v.z = fmaxf(v.z * inv, 0.f);
        v.w = fmaxf(v.w * inv, 0.f);
        *reinterpret_cast<float4*>(h + k) = v;
    }
}

// ---------------------------------------------------------------------------
// FC [B,1024] @ Wfc[1024,10] + bfc, softmax over 10. One warp per batch row.
// ---------------------------------------------------------------------------
__global__ void fc_softmax_kernel(const float* __restrict__ H,
                                  const float* __restrict__ Wfc,
                                  const float* __restrict__ bfc,
                                  float* __restrict__ out, int B)
{
    long long warp = ((long long)blockIdx.x * blockDim.x + threadIdx.x) >> 5;
    int lane = threadIdx.x & 31;
    if (warp >= B) return;

    const float* h = H + (size_t)warp * 1024;
    float acc[10];
    #pragma unroll
    for (int o = 0; o < 10; ++o) acc[o] = 0.f;

    for (int k = lane; k < 1024; k += 32) {
        float hv = h[k];
        const float* w = Wfc + (size_t)k * 10;
        #pragma unroll
        for (int o = 0; o < 10; ++o) acc[o] += hv * w[o];
    }
    #pragma unroll
    for (int o = 0; o < 10; ++o)
        #pragma unroll
        for (int off = 16; off > 0; off >>= 1)
            acc[o] += __shfl_xor_sync(0xffffffffu, acc[o], off);

    if (lane == 0) {
        float logit[10], m = -1e30f;
        #pragma unroll
        for (int o = 0; o < 10; ++o) {
            logit[o] = acc[o] + bfc[o];
            m = fmaxf(m, logit[o]);
        }
        float s = 0.f;
        #pragma unroll
        for (int o = 0; o < 10; ++o) {
            logit[o] = expf(logit[o] - m);
            s += logit[o];
        }
        float invs = 1.f / s;
        float* orow = out + (size_t)warp * 10;
        #pragma unroll
        for (int o = 0; o < 10; ++o) orow[o] = logit[o] * invs;
    }
}

// ---------------------------------------------------------------------------
extern "C" void kernel_launch(void* const* d_in, const int* in_sizes, int n_in,
                              void* d_out, int out_size)
{
    const float*     x   = (const float*)d_in[0];
    const void*      ei  = d_in[1];
    const float*     W1  = (const float*)d_in[2];
    const float*     b1  = (const float*)d_in[3];
    const float*     Wl2 = (const float*)d_in[4];
    const float*     bl2 = (const float*)d_in[5];
    const float*     Wr2 = (const float*)d_in[6];
    const float*     Wl3 = (const float*)d_in[7];
    const float*     bl3 = (const float*)d_in[8];
    const float*     Wr3 = (const float*)d_in[9];
    const float*     Wl4 = (const float*)d_in[10];
    const float*     bl4 = (const float*)d_in[11];
    const float*     Wr4 = (const float*)d_in[12];
    const float*     Wfc = (const float*)d_in[13];
    const float*     bfc = (const float*)d_in[14];

    const int B = in_sizes[0] / (4 * 64);
    const int E = in_sizes[1] / 2;
    const long long M = (long long)B * 4;

    float *bufA, *bufB, *bufC;
    cudaGetSymbolAddress((void**)&bufA, g_bufA);
    cudaGetSymbolAddress((void**)&bufB, g_bufB);
    cudaGetSymbolAddress((void**)&bufC, g_bufC);

    build_graph_kernel<<<1, 32>>>(ei, E);

    // ---- L1: GCN (premix with A, then GEMM K=64 -> 1024, relu) ----
    {
        long long t = (long long)B * (64 / 4);
        premix_kernel<<<(unsigned)((t + 255) / 256), 256>>>(x, bufB, B, 64, 0);
        sgemm_kernel<<<dim3(1024 / 128, (unsigned)(M / 128)), 256>>>(
            bufB, nullptr, W1, nullptr, b1, bufA, (int)M, 1024, 64, 1, 1);
    }
    // ---- L2: SAGE 1024 -> 512 ----
    {
        long long t = (long long)B * (1024 / 4);
        premix_kernel<<<(unsigned)((t + 255) / 256), 256>>>(bufA, bufB, B, 1024, 1);
        sgemm_kernel<<<dim3(512 / 128, (unsigned)(M / 128)), 256>>>(
            bufB, bufA, Wl2, Wr2, bl2, bufC, (int)M, 512, 1024, 2, 0);
        norm_relu_kernel<<<(unsigned)((M + 3) / 4), 128>>>(bufC, M, 512);
    }
    // ---- L3: SAGE 512 -> 256 ----
    {
        long long t = (long long)B * (512 / 4);
        premix_kernel<<<(unsigned)((t + 255) / 256), 256>>>(bufC, bufB, B, 512, 1);
        sgemm_kernel<<<dim3(256 / 128, (unsigned)(M / 128)), 256>>>(
            bufB, bufC, Wl3, Wr3, bl3, bufA, (int)M, 256, 512, 2, 0);
        norm_relu_kernel<<<(unsigned)((M + 3) / 4), 128>>>(bufA, M, 256);
    }
    // ---- L4: SAGE 256 -> 256 ----
    {
        long long t = (long long)B * (256 / 4);
        premix_kernel<<<(unsigned)((t + 255) / 256), 256>>>(bufA, bufB, B, 256, 1);
        sgemm_kernel<<<dim3(256 / 128, (unsigned)(M / 128)), 256>>>(
            bufB, bufA, Wl4, Wr4, bl4, bufC, (int)M, 256, 256, 2, 0);
        norm_relu_kernel<<<(unsigned)((M + 3) / 4), 128>>>(bufC, M, 256);
    }
    // ---- FC + softmax ----
    {
        long long warps = B;
        fc_softmax_kernel<<<(unsigned)((warps * 32 + 255) / 256), 256>>>(
            bufC, Wfc, bfc, (float*)d_out, B);
    }
}

// round 4
// speedup vs baseline: 2.1728x; 2.1728x over previous
#include <cuda_runtime.h>
#include <cuda_bf16.h>
#include <math.h>
#include <stdint.h>

// ===========================================================================
// GNN over fixed 4-node graph, B=32768 (M = 4B = 131072 rows).
// GEMMs on baseline mma.sync bf16 (2-way split: hh+hl+lh, fp32 accum).
// Graph premix (4x4) fused into GEMM A-tile load. Weights pre-split to bf16.
// (tcgen05 unavailable: harness PTX target is plain sm_103, no 'a' features.)
// ===========================================================================

#define MAXB 32768
#define PADK 72   // 64 k + 8 pad (bf16 units) -> conflict-free ldmatrix

__device__ float g_A[16];   // GCN normalized adjacency (4x4)
__device__ float g_M[16];   // SAGE mean-aggregation matrix (4x4)
__device__ float g_bufA[(size_t)MAXB * 4 * 1024];
__device__ float g_bufC[(size_t)MAXB * 4 * 1024];
// pre-split weights (bf16 hi/lo), per-layer [N][K0] row-major
__device__ __align__(16) __nv_bfloat16 g_wt_hi[1507328];
__device__ __align__(16) __nv_bfloat16 g_wt_lo[1507328];

// ---------------------------------------------------------------------------
__device__ __forceinline__ uint32_t smem_u32(const void* p) {
    uint32_t a;
    asm("{ .reg .u64 t; cvta.to.shared.u64 t, %1; cvt.u32.u64 %0, t; }"
        : "=r"(a) : "l"(p));
    return a;
}
__device__ __forceinline__ void ldsm_x4(uint32_t (&r)[4], uint32_t addr) {
    asm volatile("ldmatrix.sync.aligned.m8n8.x4.shared.b16 {%0,%1,%2,%3}, [%4];"
                 : "=r"(r[0]), "=r"(r[1]), "=r"(r[2]), "=r"(r[3]) : "r"(addr));
}
__device__ __forceinline__ void ldsm_x2(uint32_t (&r)[2], uint32_t addr) {
    asm volatile("ldmatrix.sync.aligned.m8n8.x2.shared.b16 {%0,%1}, [%2];"
                 : "=r"(r[0]), "=r"(r[1]) : "r"(addr));
}
__device__ __forceinline__ void mma_bf16(float (&d)[4], const uint32_t (&a)[4],
                                         const uint32_t (&b)[2]) {
    asm volatile(
        "mma.sync.aligned.m16n8k16.row.col.f32.bf16.bf16.f32 "
        "{%0,%1,%2,%3}, {%4,%5,%6,%7}, {%8,%9}, {%0,%1,%2,%3};"
        : "+f"(d[0]), "+f"(d[1]), "+f"(d[2]), "+f"(d[3])
        : "r"(a[0]), "r"(a[1]), "r"(a[2]), "r"(a[3]), "r"(b[0]), "r"(b[1]));
}
__device__ __forceinline__ uint32_t bf2pack(float a, float b) {
    uint32_t ua = (uint32_t)__bfloat16_as_ushort(__float2bfloat16_rn(a));
    uint32_t ub = (uint32_t)__bfloat16_as_ushort(__float2bfloat16_rn(b));
    return ua | (ub << 16);
}
__device__ __forceinline__ float bflo(float a) {
    return a - __bfloat162float(__float2bfloat16_rn(a));
}

// ---------------------------------------------------------------------------
// Build 4x4 mixing matrices from edge_index (dtype-adaptive int32/int64).
// ---------------------------------------------------------------------------
__global__ void build_graph_kernel(const void* __restrict__ ei_raw, int E)
{
    if (threadIdx.x != 0 || blockIdx.x != 0) return;
    const long long* e64 = (const long long*)ei_raw;
    const int*       e32 = (const int*)ei_raw;
    bool is64 = true;
    for (int e = 0; e < E; ++e) {
        long long v = e64[e];
        if (v < 0 || v >= 4) { is64 = false; break; }
    }
    int src[64], dst[64];
    for (int e = 0; e < E; ++e) {
        if (is64) { src[e] = (int)e64[e]; dst[e] = (int)e64[E + e]; }
        else      { src[e] = e32[e];      dst[e] = e32[E + e]; }
    }
    float degG[4] = {1.f, 1.f, 1.f, 1.f};
    float cntS[4] = {0.f, 0.f, 0.f, 0.f};
    for (int e = 0; e < E; ++e) { degG[dst[e]] += 1.f; cntS[dst[e]] += 1.f; }
    float dinv[4];
    #pragma unroll
    for (int n = 0; n < 4; ++n) dinv[n] = rsqrtf(degG[n]);
    float A[16], M[16];
    #pragma unroll
    for (int i = 0; i < 16; ++i) { A[i] = 0.f; M[i] = 0.f; }
    for (int e = 0; e < E; ++e) {
        int s = src[e], d = dst[e];
        A[d * 4 + s] += dinv[s] * dinv[d];
        M[d * 4 + s] += 1.f / fmaxf(cntS[d], 1.f);
    }
    #pragma unroll
    for (int n = 0; n < 4; ++n) A[n * 4 + n] += dinv[n] * dinv[n];
    #pragma unroll
    for (int i = 0; i < 16; ++i) { g_A[i] = A[i]; g_M[i] = M[i]; }
}

// ---------------------------------------------------------------------------
// Weight prep: split fp32 W[K0,N] (row-major) into bf16 hi/lo stored [N][K0].
// ---------------------------------------------------------------------------
__global__ void prep_w_kernel(const float* __restrict__ W, int K0, int N,
                              size_t dst_off)
{
    long long idx = (long long)blockIdx.x * 256 + threadIdx.x;
    if (idx >= (long long)K0 * N) return;
    int k = (int)(idx / N), n = (int)(idx % N);
    float v = W[idx];
    __nv_bfloat16 h = __float2bfloat16_rn(v);
    __nv_bfloat16 l = __float2bfloat16_rn(v - __bfloat162float(h));
    size_t o = dst_off + (size_t)n * K0 + k;
    g_wt_hi[o] = h;
    g_wt_lo[o] = l;
}

// ---------------------------------------------------------------------------
// Tensor-core GEMM with fused premix + bf16 split.
// C[M,N] = concat(mix(A), A)[M, K0*nparts] @ concat(W0,W1) + bias (opt relu)
// grid = (N/128, M/128); 256 threads (8 warps, 2 x 4); warp tile 64x32.
// ---------------------------------------------------------------------------
#define OFF_BIAS 0
#define OFF_A0H  512
#define OFF_A0L  (OFF_A0H + 128 * PADK * 2)
#define OFF_A1H  (OFF_A0L + 128 * PADK * 2)
#define OFF_A1L  (OFF_A1H + 128 * PADK * 2)
#define OFF_WH   (OFF_A1L + 128 * PADK * 2)
#define OFF_WL   (OFF_WH + 128 * PADK * 2)
#define SMEM_BYTES (OFF_WL + 128 * PADK * 2)

__global__ __launch_bounds__(256)
void gemm_tc_kernel(const float* __restrict__ Ain,
                    size_t w0_off, size_t w1_off,
                    const float* __restrict__ bias,
                    float* __restrict__ C,
                    int K0, int N, int nparts, int relu, int which_mat)
{
    extern __shared__ char smem[];
    const uint32_t sbase = smem_u32(smem);
    const int tid = threadIdx.x, wid = tid >> 5, lid = tid & 31;
    const int by = blockIdx.x, bm = blockIdx.y;
    const int warp_m = wid & 1, warp_n = wid >> 1;   // 2 x 4 warps
    const int m_base = warp_m * 64;                  // within 128-row tile
    const int n_base = warp_n * 32;                  // within 128-col tile

    if (tid < 128) ((float*)(smem + OFF_BIAS))[tid] = bias[by * 128 + tid];
    float mat[16];
    {
        const float* m = which_mat ? g_M : g_A;
        #pragma unroll
        for (int i = 0; i < 16; ++i) mat[i] = m[i];
    }

    float acc[4][4][4];
    #pragma unroll
    for (int mt = 0; mt < 4; ++mt)
        #pragma unroll
        for (int nt = 0; nt < 4; ++nt)
            #pragma unroll
            for (int i = 0; i < 4; ++i) acc[mt][nt][i] = 0.f;

    // ldmatrix lane addressing (constant per thread)
    const int a_r  = lid & 15;                 // row within 16-row tile
    const int a_ko = (lid >> 4) << 3;          // +8 k for lanes 16-31
    const int b_r  = lid & 7;                  // n within 8-col tile
    const int b_ko = (lid & 8);                // +8 k for lanes 8-15

    const int KC = K0 >> 6;

    for (int kc = 0; kc < KC; ++kc) {
        __syncthreads();   // previous iter's MMAs done reading A
        // ---- A chunk: 32 batch groups x 64 cols; premix + bf16 split ----
        #pragma unroll 1
        for (int it = tid; it < 512; it += 256) {
            int bl = it >> 4, s = it & 15;
            const float* base = Ain + ((size_t)bm * 128 + bl * 4) * K0
                                    + (size_t)kc * 64 + s * 4;
            float4 v[4];
            #pragma unroll
            for (int m = 0; m < 4; ++m)
                v[m] = *(const float4*)(base + (size_t)m * K0);
            if (nparts == 2) {
                #pragma unroll
                for (int m = 0; m < 4; ++m) {
                    int bo = ((bl * 4 + m) * PADK + s * 4) * 2;
                    *(uint2*)(smem + OFF_A1H + bo) =
                        make_uint2(bf2pack(v[m].x, v[m].y), bf2pack(v[m].z, v[m].w));
                    *(uint2*)(smem + OFF_A1L + bo) =
                        make_uint2(bf2pack(bflo(v[m].x), bflo(v[m].y)),
                                   bf2pack(bflo(v[m].z), bflo(v[m].w)));
                }
            }
            #pragma unroll
            for (int n = 0; n < 4; ++n) {
                float4 u;
                u.x = mat[n*4+0]*v[0].x + mat[n*4+1]*v[1].x + mat[n*4+2]*v[2].x + mat[n*4+3]*v[3].x;
                u.y = mat[n*4+0]*v[0].y + mat[n*4+1]*v[1].y + mat[n*4+2]*v[2].y + mat[n*4+3]*v[3].y;
                u.z = mat[n*4+0]*v[0].z + mat[n*4+1]*v[1].z + mat[n*4+2]*v[2].z + mat[n*4+3]*v[3].z;
                u.w = mat[n*4+0]*v[0].w + mat[n*4+1]*v[1].w + mat[n*4+2]*v[2].w + mat[n*4+3]*v[3].w;
                int bo = ((bl * 4 + n) * PADK + s * 4) * 2;
                *(uint2*)(smem + OFF_A0H + bo) =
                    make_uint2(bf2pack(u.x, u.y), bf2pack(u.z, u.w));
                *(uint2*)(smem + OFF_A0L + bo) =
                    make_uint2(bf2pack(bflo(u.x), bflo(u.y)),
                               bf2pack(bflo(u.z), bflo(u.w)));
            }
        }

        for (int part = 0; part < nparts; ++part) {
            __syncthreads();   // A ready (part 0) / prev MMAs done with W
            // ---- W tile copy: 128 n-rows x 64 k-cols (bf16 hi+lo) ----
            {
                const size_t wb = (part ? w1_off : w0_off);
                const __nv_bfloat16* srcH = g_wt_hi + wb + (size_t)by * 128 * K0
                                          + (size_t)kc * 64;
                const __nv_bfloat16* srcL = g_wt_lo + wb + (size_t)by * 128 * K0
                                          + (size_t)kc * 64;
                #pragma unroll
                for (int i = 0; i < 4; ++i) {
                    int c = tid + i * 256;          // 0..1023
                    int rr = c >> 3, cc = c & 7;    // row, uint4-col
                    uint4 vh = *(const uint4*)(srcH + (size_t)rr * K0 + cc * 8);
                    uint4 vl = *(const uint4*)(srcL + (size_t)rr * K0 + cc * 8);
                    *(uint4*)(smem + OFF_WH + (rr * PADK + cc * 8) * 2) = vh;
                    *(uint4*)(smem + OFF_WL + (rr * PADK + cc * 8) * 2) = vl;
                }
            }
            __syncthreads();   // W ready

            const uint32_t aH = sbase + (part ? OFF_A1H : OFF_A0H);
            const uint32_t aL = sbase + (part ? OFF_A1L : OFF_A0L);

            #pragma unroll
            for (int ks = 0; ks < 4; ++ks) {
                const int kof = ks * 16;
                uint32_t bh[4][2], bl2r[4][2];
                #pragma unroll
                for (int nt = 0; nt < 4; ++nt) {
                    uint32_t boff =
                        ((n_base + nt * 8 + b_r) * PADK + kof + b_ko) * 2;
                    ldsm_x2(bh[nt],   sbase + OFF_WH + boff);
                    ldsm_x2(bl2r[nt], sbase + OFF_WL + boff);
                }
                #pragma unroll
                for (int mt = 0; mt < 4; ++mt) {
                    uint32_t aoff =
                        ((m_base + mt * 16 + a_r) * PADK + kof + a_ko) * 2;
                    uint32_t ah[4], al[4];
                    ldsm_x4(ah, aH + aoff);
                    ldsm_x4(al, aL + aoff);
                    #pragma unroll
                    for (int nt = 0; nt < 4; ++nt) {
                        mma_bf16(acc[mt][nt], ah, bh[nt]);
                        mma_bf16(acc[mt][nt], ah, bl2r[nt]);
                        mma_bf16(acc[mt][nt], al, bh[nt]);
                    }
                }
            }
        }
    }

    // ---- epilogue: +bias, opt relu, float2 stores ----
    const float* bs = (const float*)(smem + OFF_BIAS);
    const int rq = lid >> 2, cq = (lid & 3) * 2;
    #pragma unroll
    for (int mt = 0; mt < 4; ++mt) {
        #pragma unroll
        for (int nt = 0; nt < 4; ++nt) {
            int col = n_base + nt * 8 + cq;
            size_t gcol = (size_t)by * 128 + col;
            float b0 = bs[col], b1 = bs[col + 1];
            size_t r0 = (size_t)bm * 128 + m_base + mt * 16 + rq;
            float2 o0, o1;
            o0.x = acc[mt][nt][0] + b0; o0.y = acc[mt][nt][1] + b1;
            o1.x = acc[mt][nt][2] + b0; o1.y = acc[mt][nt][3] + b1;
            if (relu) {
                o0.x = fmaxf(o0.x, 0.f); o0.y = fmaxf(o0.y, 0.f);
                o1.x = fmaxf(o1.x, 0.f); o1.y = fmaxf(o1.y, 0.f);
            }
            *(float2*)(C + r0 * N + gcol)       = o0;
            *(float2*)(C + (r0 + 8) * N + gcol) = o1;
        }
    }
}

// ---------------------------------------------------------------------------
// Row-wise L2 normalize + relu, in place. One warp per row.
// ---------------------------------------------------------------------------
__global__ void norm_relu_kernel(float* __restrict__ H, long long rows, int N)
{
    long long warp = ((long long)blockIdx.x * blockDim.x + threadIdx.x) >> 5;
    int lane = threadIdx.x & 31;
    if (warp >= rows) return;
    float* h = H + (size_t)warp * N;
    float ss = 0.f;
    for (int k = lane * 4; k < N; k += 128) {
        float4 v = *reinterpret_cast<const float4*>(h + k);
        ss += v.x * v.x + v.y * v.y + v.z * v.z + v.w * v.w;
    }
    #pragma unroll
    for (int off = 16; off > 0; off >>= 1)
        ss += __shfl_xor_sync(0xffffffffu, ss, off);
    float inv = 1.f / fmaxf(sqrtf(ss), 1e-12f);
    for (int k = lane * 4; k < N; k += 128) {
        float4 v = *reinterpret_cast<const float4*>(h + k);
        v.x = fmaxf(v.x * inv, 0.f);
        v.y = fmaxf(v.y * inv, 0.f);
        v.z = fmaxf(v.z * inv, 0.f);
        v.w = fmaxf(v.w * inv, 0.f);
        *reinterpret_cast<float4*>(h + k) = v;
    }
}

// ---------------------------------------------------------------------------
// FC [B,1024] @ Wfc[1024,10] + bfc, softmax. One warp per batch row.
// ---------------------------------------------------------------------------
__global__ void fc_softmax_kernel(const float* __restrict__ H,
                                  const float* __restrict__ Wfc,
                                  const float* __restrict__ bfc,
                                  float* __restrict__ out, int B)
{
    long long warp = ((long long)blockIdx.x * blockDim.x + threadIdx.x) >> 5;
    int lane = threadIdx.x & 31;
    if (warp >= B) return;
    const float* h = H + (size_t)warp * 1024;
    float acc[10];
    #pragma unroll
    for (int o = 0; o < 10; ++o) acc[o] = 0.f;
    for (int k = lane; k < 1024; k += 32) {
        float hv = h[k];
        const float* w = Wfc + (size_t)k * 10;
        #pragma unroll
        for (int o = 0; o < 10; ++o) acc[o] += hv * w[o];
    }
    #pragma unroll
    for (int o = 0; o < 10; ++o)
        #pragma unroll
        for (int off = 16; off > 0; off >>= 1)
            acc[o] += __shfl_xor_sync(0xffffffffu, acc[o], off);
    if (lane == 0) {
        float logit[10], m = -1e30f;
        #pragma unroll
        for (int o = 0; o < 10; ++o) {
            logit[o] = acc[o] + bfc[o];
            m = fmaxf(m, logit[o]);
        }
        float s = 0.f;
        #pragma unroll
        for (int o = 0; o < 10; ++o) { logit[o] = expf(logit[o] - m); s += logit[o]; }
        float invs = 1.f / s;
        float* orow = out + (size_t)warp * 10;
        #pragma unroll
        for (int o = 0; o < 10; ++o) orow[o] = logit[o] * invs;
    }
}

// ---------------------------------------------------------------------------
extern "C" void kernel_launch(void* const* d_in, const int* in_sizes, int n_in,
                              void* d_out, int out_size)
{
    const float* x   = (const float*)d_in[0];
    const void*  ei  = d_in[1];
    const float* W1  = (const float*)d_in[2];
    const float* b1  = (const float*)d_in[3];
    const float* Wl2 = (const float*)d_in[4];
    const float* bl2 = (const float*)d_in[5];
    const float* Wr2 = (const float*)d_in[6];
    const float* Wl3 = (const float*)d_in[7];
    const float* bl3 = (const float*)d_in[8];
    const float* Wr3 = (const float*)d_in[9];
    const float* Wl4 = (const float*)d_in[10];
    const float* bl4 = (const float*)d_in[11];
    const float* Wr4 = (const float*)d_in[12];
    const float* Wfc = (const float*)d_in[13];
    const float* bfc = (const float*)d_in[14];

    const int B = in_sizes[0] / (4 * 64);
    const int E = in_sizes[1] / 2;
    const long long M = (long long)B * 4;

    float *bufA, *bufC;
    cudaGetSymbolAddress((void**)&bufA, g_bufA);
    cudaGetSymbolAddress((void**)&bufC, g_bufC);

    cudaFuncSetAttribute(gemm_tc_kernel,
                         cudaFuncAttributeMaxDynamicSharedMemorySize, SMEM_BYTES);

    build_graph_kernel<<<1, 32>>>(ei, E);

    // weight prep (bf16 split), offsets in bf16 elements
    const size_t OW1 = 0, OWl2 = 65536, OWr2 = 589824, OWl3 = 1114112,
                 OWr3 = 1245184, OWl4 = 1376256, OWr4 = 1441792;
    prep_w_kernel<<<(64   * 1024 + 255) / 256, 256>>>(W1,  64,   1024, OW1);
    prep_w_kernel<<<(1024 * 512  + 255) / 256, 256>>>(Wl2, 1024, 512,  OWl2);
    prep_w_kernel<<<(1024 * 512  + 255) / 256, 256>>>(Wr2, 1024, 512,  OWr2);
    prep_w_kernel<<<(512  * 256  + 255) / 256, 256>>>(Wl3, 512,  256,  OWl3);
    prep_w_kernel<<<(512  * 256  + 255) / 256, 256>>>(Wr3, 512,  256,  OWr3);
    prep_w_kernel<<<(256  * 256  + 255) / 256, 256>>>(Wl4, 256,  256,  OWl4);
    prep_w_kernel<<<(256  * 256  + 255) / 256, 256>>>(Wr4, 256,  256,  OWr4);

    const unsigned gm = (unsigned)(M / 128);

    // L1: GCN  x[M,64] -> bufA[M,1024], relu
    gemm_tc_kernel<<<dim3(8, gm), 256, SMEM_BYTES>>>(
        x, OW1, OW1, b1, bufA, 64, 1024, 1, 1, 0);
    // L2: SAGE bufA[M,1024] -> bufC[M,512]
    gemm_tc_kernel<<<dim3(4, gm), 256, SMEM_BYTES>>>(
        bufA, OWl2, OWr2, bl2, bufC, 1024, 512, 2, 0, 1);
    norm_relu_kernel<<<(unsigned)((M + 3) / 4), 128>>>(bufC, M, 512);
    // L3: SAGE bufC[M,512] -> bufA[M,256]
    gemm_tc_kernel<<<dim3(2, gm), 256, SMEM_BYTES>>>(
        bufC, OWl3, OWr3, bl3, bufA, 512, 256, 2, 0, 1);
    norm_relu_kernel<<<(unsigned)((M + 3) / 4), 128>>>(bufA, M, 256);
    // L4: SAGE bufA[M,256] -> bufC[M,256]
    gemm_tc_kernel<<<dim3(2, gm), 256, SMEM_BYTES>>>(
        bufA, OWl4, OWr4, bl4, bufC, 256, 256, 2, 0, 1);
    norm_relu_kernel<<<(unsigned)((M + 3) / 4), 128>>>(bufC, M, 256);
    // FC + softmax
    fc_softmax_kernel<<<(unsigned)((B * 32 + 255) / 256), 256>>>(
        bufC, Wfc, bfc, (float*)d_out, B);
}

// round 5
// speedup vs baseline: 2.4175x; 1.1126x over previous
#include <cuda_runtime.h>
#include <cuda_bf16.h>
#include <math.h>
#include <stdint.h>

// ===========================================================================
// GNN over fixed 4-node graph, B=32768 (M = 4B = 131072 rows).
// Plain GEMMs on mma.sync bf16 (2-way split: hh+hl+lh, fp32 accum),
// N-concat weights [Wl|Wr]; 4x4 graph mixing applied as fp32 POST-pass
// fused with bias + l2norm + relu. cp.async double-buffered W tiles.
// ===========================================================================

#define MAXB 32768
#define PADK 72   // 64 k + 8 pad (bf16) -> conflict-free ldmatrix, 144B rows

__device__ float g_A[16];   // GCN normalized adjacency (4x4)
__device__ float g_M[16];   // SAGE mean-aggregation matrix (4x4)
__device__ float g_bufA[(size_t)MAXB * 4 * 1024];
__device__ float g_bufC[(size_t)MAXB * 4 * 1024];
// pre-split weights (bf16 hi/lo), per-layer [Ntot][K0] row-major
__device__ __align__(16) __nv_bfloat16 g_wt_hi[1507328];
__device__ __align__(16) __nv_bfloat16 g_wt_lo[1507328];

// ---------------------------------------------------------------------------
__device__ __forceinline__ uint32_t smem_u32(const void* p) {
    uint32_t a;
    asm("{ .reg .u64 t; cvta.to.shared.u64 t, %1; cvt.u32.u64 %0, t; }"
        : "=r"(a) : "l"(p));
    return a;
}
__device__ __forceinline__ void ldsm_x4(uint32_t (&r)[4], uint32_t addr) {
    asm volatile("ldmatrix.sync.aligned.m8n8.x4.shared.b16 {%0,%1,%2,%3}, [%4];"
                 : "=r"(r[0]), "=r"(r[1]), "=r"(r[2]), "=r"(r[3]) : "r"(addr));
}
__device__ __forceinline__ void ldsm_x2(uint32_t (&r)[2], uint32_t addr) {
    asm volatile("ldmatrix.sync.aligned.m8n8.x2.shared.b16 {%0,%1}, [%2];"
                 : "=r"(r[0]), "=r"(r[1]) : "r"(addr));
}
__device__ __forceinline__ void mma_bf16(float (&d)[4], const uint32_t (&a)[4],
                                         const uint32_t (&b)[2]) {
    asm volatile(
        "mma.sync.aligned.m16n8k16.row.col.f32.bf16.bf16.f32 "
        "{%0,%1,%2,%3}, {%4,%5,%6,%7}, {%8,%9}, {%0,%1,%2,%3};"
        : "+f"(d[0]), "+f"(d[1]), "+f"(d[2]), "+f"(d[3])
        : "r"(a[0]), "r"(a[1]), "r"(a[2]), "r"(a[3]), "r"(b[0]), "r"(b[1]));
}
__device__ __forceinline__ void cp_async16(uint32_t dst, const void* src) {
    asm volatile("cp.async.cg.shared.global [%0], [%1], 16;"
                 :: "r"(dst), "l"(src));
}
#define CP_COMMIT() asm volatile("cp.async.commit_group;" ::: "memory")
#define CP_WAIT0()  asm volatile("cp.async.wait_group 0;" ::: "memory")

__device__ __forceinline__ uint32_t bf2pack(float a, float b) {
    uint32_t ua = (uint32_t)__bfloat16_as_ushort(__float2bfloat16_rn(a));
    uint32_t ub = (uint32_t)__bfloat16_as_ushort(__float2bfloat16_rn(b));
    return ua | (ub << 16);
}
__device__ __forceinline__ float bflo(float a) {
    return a - __bfloat162float(__float2bfloat16_rn(a));
}

// ---------------------------------------------------------------------------
// Build 4x4 mixing matrices from edge_index (dtype-adaptive int32/int64).
// ---------------------------------------------------------------------------
__global__ void build_graph_kernel(const void* __restrict__ ei_raw, int E)
{
    if (threadIdx.x != 0 || blockIdx.x != 0) return;
    const long long* e64 = (const long long*)ei_raw;
    const int*       e32 = (const int*)ei_raw;
    bool is64 = true;
    for (int e = 0; e < E; ++e) {
        long long v = e64[e];
        if (v < 0 || v >= 4) { is64 = false; break; }
    }
    int src[64], dst[64];
    for (int e = 0; e < E; ++e) {
        if (is64) { src[e] = (int)e64[e]; dst[e] = (int)e64[E + e]; }
        else      { src[e] = e32[e];      dst[e] = e32[E + e]; }
    }
    float degG[4] = {1.f, 1.f, 1.f, 1.f};
    float cntS[4] = {0.f, 0.f, 0.f, 0.f};
    for (int e = 0; e < E; ++e) { degG[dst[e]] += 1.f; cntS[dst[e]] += 1.f; }
    float dinv[4];
    #pragma unroll
    for (int n = 0; n < 4; ++n) dinv[n] = rsqrtf(degG[n]);
    float A[16], M[16];
    #pragma unroll
    for (int i = 0; i < 16; ++i) { A[i] = 0.f; M[i] = 0.f; }
    for (int e = 0; e < E; ++e) {
        int s = src[e], d = dst[e];
        A[d * 4 + s] += dinv[s] * dinv[d];
        M[d * 4 + s] += 1.f / fmaxf(cntS[d], 1.f);
    }
    #pragma unroll
    for (int n = 0; n < 4; ++n) A[n * 4 + n] += dinv[n] * dinv[n];
    #pragma unroll
    for (int i = 0; i < 16; ++i) { g_A[i] = A[i]; g_M[i] = M[i]; }
}

// ---------------------------------------------------------------------------
// Weight prep: split fp32 W[K0,N] (row-major) into bf16 hi/lo stored [N][K0].
// ---------------------------------------------------------------------------
__global__ void prep_w_kernel(const float* __restrict__ W, int K0, int N,
                              size_t dst_off)
{
    long long idx = (long long)blockIdx.x * 256 + threadIdx.x;
    if (idx >= (long long)K0 * N) return;
    int k = (int)(idx / N), n = (int)(idx % N);
    float v = W[idx];
    __nv_bfloat16 h = __float2bfloat16_rn(v);
    __nv_bfloat16 l = __float2bfloat16_rn(v - __bfloat162float(h));
    size_t o = dst_off + (size_t)n * K0 + k;
    g_wt_hi[o] = h;
    g_wt_lo[o] = l;
}

// ---------------------------------------------------------------------------
// Plain bf16-split tensor-core GEMM: C[M,Ntot] = A[M,K0] @ W[K0,Ntot] (fp32 out)
// grid = (Ntot/128, M/128); 256 threads (8 warps 2x4); warp tile 64x32.
// W double-buffered via cp.async; A prefetched in registers.
// ---------------------------------------------------------------------------
#define OFF_AH  0
#define OFF_AL  (128 * PADK * 2)
#define OFF_W0H (2 * 128 * PADK * 2)
#define OFF_W0L (3 * 128 * PADK * 2)
#define OFF_W1H (4 * 128 * PADK * 2)
#define OFF_W1L (5 * 128 * PADK * 2)
#define SMEM_BYTES (6 * 128 * PADK * 2)

__global__ __launch_bounds__(256)
void gemm_tc_kernel(const float* __restrict__ Ain, size_t w_off,
                    float* __restrict__ C, int K0, int Ntot)
{
    extern __shared__ char smem[];
    const uint32_t sbase = smem_u32(smem);
    const int tid = threadIdx.x, wid = tid >> 5, lid = tid & 31;
    const int by = blockIdx.x, bm = blockIdx.y;
    const int warp_m = wid & 1, warp_n = wid >> 1;
    const int m_base = warp_m * 64, n_base = warp_n * 32;

    float acc[4][4][4];
    #pragma unroll
    for (int mt = 0; mt < 4; ++mt)
        #pragma unroll
        for (int nt = 0; nt < 4; ++nt)
            #pragma unroll
            for (int i = 0; i < 4; ++i) acc[mt][nt][i] = 0.f;

    const int a_r  = lid & 15;
    const int a_ko = (lid >> 4) << 3;
    const int b_r  = lid & 7;
    const int b_ko = (lid & 8);

    const int KC = K0 >> 6;
    const float* Abase = Ain + (size_t)bm * 128 * K0;
    const __nv_bfloat16* WHbase = g_wt_hi + w_off + (size_t)by * 128 * K0;
    const __nv_bfloat16* WLbase = g_wt_lo + w_off + (size_t)by * 128 * K0;

    // A-load register staging (8 float4 per thread = 128x64 tile)
    float4 av[8];
    #pragma unroll
    for (int i = 0; i < 8; ++i) {
        int idx = tid + i * 256, row = idx >> 4, c4 = idx & 15;
        av[i] = *(const float4*)(Abase + (size_t)row * K0 + c4 * 4);
    }
    // W tile 0 -> buffer 0
    {
        #pragma unroll
        for (int i = 0; i < 4; ++i) {
            int c = tid + i * 256, rr = c >> 3, cc = c & 7;
            uint32_t so = (uint32_t)(rr * PADK + cc * 8) * 2;
            const size_t go = (size_t)rr * K0 + cc * 8;
            cp_async16(sbase + OFF_W0H + so, WHbase + go);
            cp_async16(sbase + OFF_W0L + so, WLbase + go);
        }
        CP_COMMIT();
    }

    for (int kc = 0; kc < KC; ++kc) {
        // store staged A (hi/lo bf16) into smem
        #pragma unroll
        for (int i = 0; i < 8; ++i) {
            int idx = tid + i * 256, row = idx >> 4, c4 = idx & 15;
            uint32_t bo = (uint32_t)(row * PADK + c4 * 4) * 2;
            *(uint2*)(smem + OFF_AH + bo) =
                make_uint2(bf2pack(av[i].x, av[i].y), bf2pack(av[i].z, av[i].w));
            *(uint2*)(smem + OFF_AL + bo) =
                make_uint2(bf2pack(bflo(av[i].x), bflo(av[i].y)),
                           bf2pack(bflo(av[i].z), bflo(av[i].w)));
        }
        CP_WAIT0();
        __syncthreads();     // A(kc) + W(kc) visible

        if (kc + 1 < KC) {
            // prefetch W(kc+1) into other buffer, A(kc+1) into regs
            uint32_t dH = sbase + (((kc + 1) & 1) ? OFF_W1H : OFF_W0H);
            uint32_t dL = sbase + (((kc + 1) & 1) ? OFF_W1L : OFF_W0L);
            #pragma unroll
            for (int i = 0; i < 4; ++i) {
                int c = tid + i * 256, rr = c >> 3, cc = c & 7;
                uint32_t so = (uint32_t)(rr * PADK + cc * 8) * 2;
                const size_t go = (size_t)rr * K0 + (kc + 1) * 64 + cc * 8;
                cp_async16(dH + so, WHbase + go);
                cp_async16(dL + so, WLbase + go);
            }
            CP_COMMIT();
            #pragma unroll
            for (int i = 0; i < 8; ++i) {
                int idx = tid + i * 256, row = idx >> 4, c4 = idx & 15;
                av[i] = *(const float4*)(Abase + (size_t)row * K0
                                         + (kc + 1) * 64 + c4 * 4);
            }
        }

        const uint32_t whb = sbase + ((kc & 1) ? OFF_W1H : OFF_W0H);
        const uint32_t wlb = sbase + ((kc & 1) ? OFF_W1L : OFF_W0L);
        #pragma unroll
        for (int ks = 0; ks < 4; ++ks) {
            const int kof = ks * 16;
            uint32_t bh[4][2], bl2r[4][2];
            #pragma unroll
            for (int nt = 0; nt < 4; ++nt) {
                uint32_t boff = (uint32_t)((n_base + nt * 8 + b_r) * PADK
                                           + kof + b_ko) * 2;
                ldsm_x2(bh[nt],   whb + boff);
                ldsm_x2(bl2r[nt], wlb + boff);
            }
            #pragma unroll
            for (int mt = 0; mt < 4; ++mt) {
                uint32_t aoff = (uint32_t)((m_base + mt * 16 + a_r) * PADK
                                           + kof + a_ko) * 2;
                uint32_t ah[4], al[4];
                ldsm_x4(ah, sbase + OFF_AH + aoff);
                ldsm_x4(al, sbase + OFF_AL + aoff);
                #pragma unroll
                for (int nt = 0; nt < 4; ++nt) {
                    mma_bf16(acc[mt][nt], ah, bh[nt]);
                    mma_bf16(acc[mt][nt], ah, bl2r[nt]);
                    mma_bf16(acc[mt][nt], al, bh[nt]);
                }
            }
        }
        __syncthreads();     // done reading A/W before next overwrite
    }

    // ---- epilogue: raw fp32 store (bias/relu/norm in post pass) ----
    const int rq = lid >> 2, cq = (lid & 3) * 2;
    #pragma unroll
    for (int mt = 0; mt < 4; ++mt) {
        #pragma unroll
        for (int nt = 0; nt < 4; ++nt) {
            size_t gcol = (size_t)by * 128 + n_base + nt * 8 + cq;
            size_t r0 = (size_t)bm * 128 + m_base + mt * 16 + rq;
            *(float2*)(C + r0 * Ntot + gcol) =
                make_float2(acc[mt][nt][0], acc[mt][nt][1]);
            *(float2*)(C + (r0 + 8) * Ntot + gcol) =
                make_float2(acc[mt][nt][2], acc[mt][nt][3]);
        }
    }
}

// ---------------------------------------------------------------------------
// GCN post: out[b,n,f] = relu( sum_m A[n,m] * P[b,m,f] + bias[f] ). F=1024.
// ---------------------------------------------------------------------------
__global__ void gcn_post_kernel(const float* __restrict__ P,
                                const float* __restrict__ bias,
                                float* __restrict__ out, int B, int F)
{
    int f4cnt = F >> 2;
    long long idx = (long long)blockIdx.x * blockDim.x + threadIdx.x;
    if (idx >= (long long)B * f4cnt) return;
    int f4 = (int)(idx % f4cnt);
    long long b = idx / f4cnt;
    float mat[16];
    #pragma unroll
    for (int i = 0; i < 16; ++i) mat[i] = g_A[i];

    const float4* Pb = (const float4*)P + b * 4 * f4cnt;
    float4*       Ob = (float4*)out     + b * 4 * f4cnt;
    float4 bv = ((const float4*)bias)[f4];
    float4 v[4];
    #pragma unroll
    for (int m = 0; m < 4; ++m) v[m] = Pb[(size_t)m * f4cnt + f4];
    #pragma unroll
    for (int n = 0; n < 4; ++n) {
        float4 r;
        r.x = fmaxf(mat[n*4+0]*v[0].x + mat[n*4+1]*v[1].x + mat[n*4+2]*v[2].x + mat[n*4+3]*v[3].x + bv.x, 0.f);
        r.y = fmaxf(mat[n*4+0]*v[0].y + mat[n*4+1]*v[1].y + mat[n*4+2]*v[2].y + mat[n*4+3]*v[3].y + bv.y, 0.f);
        r.z = fmaxf(mat[n*4+0]*v[0].z + mat[n*4+1]*v[1].z + mat[n*4+2]*v[2].z + mat[n*4+3]*v[3].z + bv.z, 0.f);
        r.w = fmaxf(mat[n*4+0]*v[0].w + mat[n*4+1]*v[1].w + mat[n*4+2]*v[2].w + mat[n*4+3]*v[3].w + bv.w, 0.f);
        Ob[(size_t)n * f4cnt + f4] = r;
    }
}

// ---------------------------------------------------------------------------
// SAGE post: P[M, 2N] = [Pl | Pr].  out[b,n,:] =
//   relu( l2norm( Mix.Pl[b,:,:] (row n) + Pr[b,n,:] + bias ) )
// One block per batch; blockDim = N/4 (128 for N=512, 64 for N=256).
// ---------------------------------------------------------------------------
__global__ void sage_post_kernel(const float* __restrict__ P,
                                 const float* __restrict__ bias,
                                 float* __restrict__ out, int N)
{
    __shared__ float red[4][4];
    const int b = blockIdx.x, tid = threadIdx.x;
    const int wid = tid >> 5, lane = tid & 31;
    const int nw = blockDim.x >> 5;
    float mat[16];
    #pragma unroll
    for (int i = 0; i < 16; ++i) mat[i] = g_M[i];

    const float* Pb = P + (size_t)b * 4 * (2 * N);
    const int f = tid * 4;
    float4 pl[4];
    #pragma unroll
    for (int m = 0; m < 4; ++m)
        pl[m] = *(const float4*)(Pb + (size_t)m * 2 * N + f);
    float4 bv = *(const float4*)(bias + f);

    float4 y[4];
    float ss[4];
    #pragma unroll
    for (int n = 0; n < 4; ++n) {
        float4 pr = *(const float4*)(Pb + (size_t)n * 2 * N + N + f);
        float4 r;
        r.x = mat[n*4+0]*pl[0].x + mat[n*4+1]*pl[1].x + mat[n*4+2]*pl[2].x + mat[n*4+3]*pl[3].x + pr.x + bv.x;
        r.y = mat[n*4+0]*pl[0].y + mat[n*4+1]*pl[1].y + mat[n*4+2]*pl[2].y + mat[n*4+3]*pl[3].y + pr.y + bv.y;
        r.z = mat[n*4+0]*pl[0].z + mat[n*4+1]*pl[1].z + mat[n*4+2]*pl[2].z + mat[n*4+3]*pl[3].z + pr.z + bv.z;
        r.w = mat[n*4+0]*pl[0].w + mat[n*4+1]*pl[1].w + mat[n*4+2]*pl[2].w + mat[n*4+3]*pl[3].w + pr.w + bv.w;
        y[n] = r;
        ss[n] = r.x * r.x + r.y * r.y + r.z * r.z + r.w * r.w;
    }
    #pragma unroll
    for (int n = 0; n < 4; ++n)
        #pragma unroll
        for (int off = 16; off > 0; off >>= 1)
            ss[n] += __shfl_xor_sync(0xffffffffu, ss[n], off);
    if (lane == 0) {
        #pragma unroll
        for (int n = 0; n < 4; ++n) red[n][wid] = ss[n];
    }
    __syncthreads();
    float inv[4];
    #pragma unroll
    for (int n = 0; n < 4; ++n) {
        float t = 0.f;
        for (int w = 0; w < nw; ++w) t += red[n][w];
        inv[n] = 1.f / fmaxf(sqrtf(t), 1e-12f);
    }
    #pragma unroll
    for (int n = 0; n < 4; ++n) {
        float4 o;
        o.x = fmaxf(y[n].x * inv[n], 0.f);
        o.y = fmaxf(y[n].y * inv[n], 0.f);
        o.z = fmaxf(y[n].z * inv[n], 0.f);
        o.w = fmaxf(y[n].w * inv[n], 0.f);
        *(float4*)(out + ((size_t)b * 4 + n) * N + f) = o;
    }
}

// ---------------------------------------------------------------------------
// FC [B,1024] @ Wfc[1024,10] + bfc, softmax. One warp per batch row.
// ---------------------------------------------------------------------------
__global__ void fc_softmax_kernel(const float* __restrict__ H,
                                  const float* __restrict__ Wfc,
                                  const float* __restrict__ bfc,
                                  float* __restrict__ out, int B)
{
    long long warp = ((long long)blockIdx.x * blockDim.x + threadIdx.x) >> 5;
    int lane = threadIdx.x & 31;
    if (warp >= B) return;
    const float* h = H + (size_t)warp * 1024;
    float acc[10];
    #pragma unroll
    for (int o = 0; o < 10; ++o) acc[o] = 0.f;
    for (int k = lane; k < 1024; k += 32) {
        float hv = h[k];
        const float* w = Wfc + (size_t)k * 10;
        #pragma unroll
        for (int o = 0; o < 10; ++o) acc[o] += hv * w[o];
    }
    #pragma unroll
    for (int o = 0; o < 10; ++o)
        #pragma unroll
        for (int off = 16; off > 0; off >>= 1)
            acc[o] += __shfl_xor_sync(0xffffffffu, acc[o], off);
    if (lane == 0) {
        float logit[10], m = -1e30f;
        #pragma unroll
        for (int o = 0; o < 10; ++o) {
            logit[o] = acc[o] + bfc[o];
            m = fmaxf(m, logit[o]);
        }
        float s = 0.f;
        #pragma unroll
        for (int o = 0; o < 10; ++o) { logit[o] = expf(logit[o] - m); s += logit[o]; }
        float invs = 1.f / s;
        float* orow = out + (size_t)warp * 10;
        #pragma unroll
        for (int o = 0; o < 10; ++o) orow[o] = logit[o] * invs;
    }
}

// ---------------------------------------------------------------------------
extern "C" void kernel_launch(void* const* d_in, const int* in_sizes, int n_in,
                              void* d_out, int out_size)
{
    const float* x   = (const float*)d_in[0];
    const void*  ei  = d_in[1];
    const float* W1  = (const float*)d_in[2];
    const float* b1  = (const float*)d_in[3];
    const float* Wl2 = (const float*)d_in[4];
    const float* bl2 = (const float*)d_in[5];
    const float* Wr2 = (const float*)d_in[6];
    const float* Wl3 = (const float*)d_in[7];
    const float* bl3 = (const float*)d_in[8];
    const float* Wr3 = (const float*)d_in[9];
    const float* Wl4 = (const float*)d_in[10];
    const float* bl4 = (const float*)d_in[11];
    const float* Wr4 = (const float*)d_in[12];
    const float* Wfc = (const float*)d_in[13];
    const float* bfc = (const float*)d_in[14];

    const int B = in_sizes[0] / (4 * 64);
    const int E = in_sizes[1] / 2;
    const long long M = (long long)B * 4;

    float *bufA, *bufC;
    cudaGetSymbolAddress((void**)&bufA, g_bufA);
    cudaGetSymbolAddress((void**)&bufC, g_bufC);

    cudaFuncSetAttribute(gemm_tc_kernel,
                         cudaFuncAttributeMaxDynamicSharedMemorySize, SMEM_BYTES);

    build_graph_kernel<<<1, 32>>>(ei, E);

    // weight prep: N-concat layout [Ntot][K0], offsets in bf16 elements
    const size_t OW1 = 0;                       // [1024][64]
    const size_t OW2 = 65536;                   // [1024][1024] = [Wl2|Wr2]
    const size_t OW3 = OW2 + 1048576;           // [512][512]  = [Wl3|Wr3]
    const size_t OW4 = OW3 + 262144;            // [512][256]  = [Wl4|Wr4]
    prep_w_kernel<<<(64   * 1024 + 255) / 256, 256>>>(W1,  64,   1024, OW1);
    prep_w_kernel<<<(1024 * 512  + 255) / 256, 256>>>(Wl2, 1024, 512,  OW2);
    prep_w_kernel<<<(1024 * 512  + 255) / 256, 256>>>(Wr2, 1024, 512,  OW2 + (size_t)512 * 1024);
    prep_w_kernel<<<(512  * 256  + 255) / 256, 256>>>(Wl3, 512,  256,  OW3);
    prep_w_kernel<<<(512  * 256  + 255) / 256, 256>>>(Wr3, 512,  256,  OW3 + (size_t)256 * 512);
    prep_w_kernel<<<(256  * 256  + 255) / 256, 256>>>(Wl4, 256,  256,  OW4);
    prep_w_kernel<<<(256  * 256  + 255) / 256, 256>>>(Wr4, 256,  256,  OW4 + (size_t)256 * 256);

    const unsigned gm = (unsigned)(M / 128);

    // L1: P1 = x @ W1  [M,1024];  h1 = relu(Mix.P1 + b1)
    gemm_tc_kernel<<<dim3(8, gm), 256, SMEM_BYTES>>>(x, OW1, bufA, 64, 1024);
    gcn_post_kernel<<<(unsigned)(((long long)B * 256 + 255) / 256), 256>>>(
        bufA, b1, bufC, B, 1024);
    // L2: P2 = h1 @ [Wl2|Wr2]  [M,1024];  h2 = sage_post(P2) [M,512]
    gemm_tc_kernel<<<dim3(8, gm), 256, SMEM_BYTES>>>(bufC, OW2, bufA, 1024, 1024);
    sage_post_kernel<<<B, 128>>>(bufA, bl2, bufC, 512);
    // L3: P3 = h2 @ [Wl3|Wr3]  [M,512];  h3 [M,256]
    gemm_tc_kernel<<<dim3(4, gm), 256, SMEM_BYTES>>>(bufC, OW3, bufA, 512, 512);
    sage_post_kernel<<<B, 64>>>(bufA, bl3, bufC, 256);
    // L4: P4 = h3 @ [Wl4|Wr4]  [M,512];  h4 [M,256]
    gemm_tc_kernel<<<dim3(4, gm), 256, SMEM_BYTES>>>(bufC, OW4, bufA, 256, 512);
    sage_post_kernel<<<B, 64>>>(bufA, bl4, bufC, 256);
    // FC + softmax
    fc_softmax_kernel<<<(unsigned)((B * 32 + 255) / 256), 256>>>(
        bufC, Wfc, bfc, (float*)d_out, B);
}

// round 6
// speedup vs baseline: 2.6983x; 1.1161x over previous
#include <cuda_runtime.h>
#include <cuda_bf16.h>
#include <math.h>
#include <stdint.h>

// ===========================================================================
// GNN over fixed 4-node graph, B=32768 (M = 4B = 131072 rows).
// GEMMs: mma.sync bf16, 2-way operand split (hh+hl+lh, fp32 accum).
// Activations stored as bf16 hi/lo pairs (split done in fused post-passes),
// so the GEMM is a pure cp.async double-buffered tensor-core loop.
// Graph mixing (4x4) fused into post-passes (mix-after-GEMM identity).
// ===========================================================================

#define MAXB 32768
#define PADK 72                 // 64 + 8 pad (bf16) -> conflict-free ldmatrix
#define TILE_B (128 * PADK * 2) // 18432 bytes per 128x64 bf16 tile
#define STAGE_B (4 * TILE_B)    // AH, AL, WH, WL
#define SMEM_BYTES (2 * STAGE_B)

__device__ float g_A[16];   // GCN normalized adjacency (4x4)
__device__ float g_M[16];   // SAGE mean-aggregation matrix (4x4)
__device__ float g_bufA[(size_t)MAXB * 4 * 1024];                   // fp32 GEMM out
__device__ __align__(16) __nv_bfloat16 g_hh[(size_t)MAXB * 4 * 1024]; // act hi
__device__ __align__(16) __nv_bfloat16 g_hl[(size_t)MAXB * 4 * 1024]; // act lo
__device__ __align__(16) __nv_bfloat16 g_wt_hi[1507328];
__device__ __align__(16) __nv_bfloat16 g_wt_lo[1507328];

// ---------------------------------------------------------------------------
__device__ __forceinline__ uint32_t smem_u32(const void* p) {
    uint32_t a;
    asm("{ .reg .u64 t; cvta.to.shared.u64 t, %1; cvt.u32.u64 %0, t; }"
        : "=r"(a) : "l"(p));
    return a;
}
__device__ __forceinline__ void ldsm_x4(uint32_t (&r)[4], uint32_t addr) {
    asm volatile("ldmatrix.sync.aligned.m8n8.x4.shared.b16 {%0,%1,%2,%3}, [%4];"
                 : "=r"(r[0]), "=r"(r[1]), "=r"(r[2]), "=r"(r[3]) : "r"(addr));
}
__device__ __forceinline__ void ldsm_x2(uint32_t (&r)[2], uint32_t addr) {
    asm volatile("ldmatrix.sync.aligned.m8n8.x2.shared.b16 {%0,%1}, [%2];"
                 : "=r"(r[0]), "=r"(r[1]) : "r"(addr));
}
__device__ __forceinline__ void mma_bf16(float (&d)[4], const uint32_t (&a)[4],
                                         const uint32_t (&b)[2]) {
    asm volatile(
        "mma.sync.aligned.m16n8k16.row.col.f32.bf16.bf16.f32 "
        "{%0,%1,%2,%3}, {%4,%5,%6,%7}, {%8,%9}, {%0,%1,%2,%3};"
        : "+f"(d[0]), "+f"(d[1]), "+f"(d[2]), "+f"(d[3])
        : "r"(a[0]), "r"(a[1]), "r"(a[2]), "r"(a[3]), "r"(b[0]), "r"(b[1]));
}
__device__ __forceinline__ void cp_async16(uint32_t dst, const void* src) {
    asm volatile("cp.async.cg.shared.global [%0], [%1], 16;"
                 :: "r"(dst), "l"(src));
}
#define CP_COMMIT() asm volatile("cp.async.commit_group;" ::: "memory")
#define CP_WAIT0()  asm volatile("cp.async.wait_group 0;" ::: "memory")

__device__ __forceinline__ uint32_t bf2pack(float a, float b) {
    uint32_t ua = (uint32_t)__bfloat16_as_ushort(__float2bfloat16_rn(a));
    uint32_t ub = (uint32_t)__bfloat16_as_ushort(__float2bfloat16_rn(b));
    return ua | (ub << 16);
}
__device__ __forceinline__ float bflo(float a) {
    return a - __bfloat162float(__float2bfloat16_rn(a));
}
// write 4 consecutive (hi,lo) bf16 pairs at element offset e
__device__ __forceinline__ void store_split4(__nv_bfloat16* Hh, __nv_bfloat16* Hl,
                                             size_t e, float4 v) {
    *(uint2*)(Hh + e) = make_uint2(bf2pack(v.x, v.y), bf2pack(v.z, v.w));
    *(uint2*)(Hl + e) = make_uint2(bf2pack(bflo(v.x), bflo(v.y)),
                                   bf2pack(bflo(v.z), bflo(v.w)));
}

// ---------------------------------------------------------------------------
// Build 4x4 mixing matrices from edge_index (dtype-adaptive int32/int64).
// ---------------------------------------------------------------------------
__global__ void build_graph_kernel(const void* __restrict__ ei_raw, int E)
{
    if (threadIdx.x != 0 || blockIdx.x != 0) return;
    const long long* e64 = (const long long*)ei_raw;
    const int*       e32 = (const int*)ei_raw;
    bool is64 = true;
    for (int e = 0; e < E; ++e) {
        long long v = e64[e];
        if (v < 0 || v >= 4) { is64 = false; break; }
    }
    int src[64], dst[64];
    for (int e = 0; e < E; ++e) {
        if (is64) { src[e] = (int)e64[e]; dst[e] = (int)e64[E + e]; }
        else      { src[e] = e32[e];      dst[e] = e32[E + e]; }
    }
    float degG[4] = {1.f, 1.f, 1.f, 1.f};
    float cntS[4] = {0.f, 0.f, 0.f, 0.f};
    for (int e = 0; e < E; ++e) { degG[dst[e]] += 1.f; cntS[dst[e]] += 1.f; }
    float dinv[4];
    #pragma unroll
    for (int n = 0; n < 4; ++n) dinv[n] = rsqrtf(degG[n]);
    float A[16], M[16];
    #pragma unroll
    for (int i = 0; i < 16; ++i) { A[i] = 0.f; M[i] = 0.f; }
    for (int e = 0; e < E; ++e) {
        int s = src[e], d = dst[e];
        A[d * 4 + s] += dinv[s] * dinv[d];
        M[d * 4 + s] += 1.f / fmaxf(cntS[d], 1.f);
    }
    #pragma unroll
    for (int n = 0; n < 4; ++n) A[n * 4 + n] += dinv[n] * dinv[n];
    #pragma unroll
    for (int i = 0; i < 16; ++i) { g_A[i] = A[i]; g_M[i] = M[i]; }
}

// ---------------------------------------------------------------------------
// Weight prep: split fp32 W[K0,N] (row-major) into bf16 hi/lo stored [N][K0].
// ---------------------------------------------------------------------------
__global__ void prep_w_kernel(const float* __restrict__ W, int K0, int N,
                              size_t dst_off)
{
    long long idx = (long long)blockIdx.x * 256 + threadIdx.x;
    if (idx >= (long long)K0 * N) return;
    int k = (int)(idx / N), n = (int)(idx % N);
    float v = W[idx];
    __nv_bfloat16 h = __float2bfloat16_rn(v);
    __nv_bfloat16 l = __float2bfloat16_rn(v - __bfloat162float(h));
    size_t o = dst_off + (size_t)n * K0 + k;
    g_wt_hi[o] = h;
    g_wt_lo[o] = l;
}

// ---------------------------------------------------------------------------
// Split fp32 X[n] into bf16 hi/lo (for the network input x).
// ---------------------------------------------------------------------------
__global__ void split_x_kernel(const float* __restrict__ X, long long n4)
{
    long long i = (long long)blockIdx.x * 256 + threadIdx.x;
    if (i >= n4) return;
    float4 v = ((const float4*)X)[i];
    store_split4(g_hh, g_hl, (size_t)i * 4, v);
}

// ---------------------------------------------------------------------------
// bf16-split tensor-core GEMM: C[M,Ntot] = (Ah+Al)[M,K0] @ (Wh+Wl)[K0,Ntot]
// grid = (Ntot/128, M/128); 256 threads (8 warps 2x4); warp tile 64x32.
// All operands cp.async double-buffered; one __syncthreads per k-chunk.
// ---------------------------------------------------------------------------
__global__ __launch_bounds__(256)
void gemm_tc_kernel(const __nv_bfloat16* __restrict__ Ah,
                    const __nv_bfloat16* __restrict__ Al,
                    size_t w_off, float* __restrict__ C, int K0, int Ntot)
{
    extern __shared__ char smem[];
    const uint32_t sbase = smem_u32(smem);
    const int tid = threadIdx.x, wid = tid >> 5, lid = tid & 31;
    const int by = blockIdx.x, bm = blockIdx.y;
    const int warp_m = wid & 1, warp_n = wid >> 1;
    const int m_base = warp_m * 64, n_base = warp_n * 32;

    float acc[4][4][4];
    #pragma unroll
    for (int mt = 0; mt < 4; ++mt)
        #pragma unroll
        for (int nt = 0; nt < 4; ++nt)
            #pragma unroll
            for (int i = 0; i < 4; ++i) acc[mt][nt][i] = 0.f;

    const int a_r  = lid & 15;
    const int a_ko = (lid >> 4) << 3;
    const int b_r  = lid & 7;
    const int b_ko = (lid & 8);

    const int KC = K0 >> 6;
    const __nv_bfloat16* AHb = Ah + (size_t)bm * 128 * K0;
    const __nv_bfloat16* ALb = Al + (size_t)bm * 128 * K0;
    const __nv_bfloat16* WHb = g_wt_hi + w_off + (size_t)by * 128 * K0;
    const __nv_bfloat16* WLb = g_wt_lo + w_off + (size_t)by * 128 * K0;

    // per-thread cp.async slots: 4 lines per tensor (1024 lines / 256 thr)
    const int pc = tid;   // base slot
    auto prefetch = [&](int kc, int st) {
        uint32_t sb = sbase + st * STAGE_B;
        #pragma unroll
        for (int i = 0; i < 4; ++i) {
            int c = pc + i * 256, r = c >> 3, q = c & 7;
            uint32_t so = (uint32_t)(r * PADK + q * 8) * 2;
            size_t go = (size_t)r * K0 + (size_t)kc * 64 + q * 8;
            cp_async16(sb + so,              AHb + go);
            cp_async16(sb + TILE_B + so,     ALb + go);
            cp_async16(sb + 2 * TILE_B + so, WHb + go);
            cp_async16(sb + 3 * TILE_B + so, WLb + go);
        }
        CP_COMMIT();
    };

    prefetch(0, 0);

    for (int kc = 0; kc < KC; ++kc) {
        CP_WAIT0();
        __syncthreads();          // tile kc visible; all MMA(kc-1) complete
        if (kc + 1 < KC) prefetch(kc + 1, (kc + 1) & 1);

        const uint32_t sb = sbase + (kc & 1) * STAGE_B;
        #pragma unroll
        for (int ks = 0; ks < 4; ++ks) {
            const int kof = ks * 16;
            uint32_t bh[4][2], bl2[4][2];
            #pragma unroll
            for (int nt = 0; nt < 4; ++nt) {
                uint32_t boff = (uint32_t)((n_base + nt * 8 + b_r) * PADK
                                           + kof + b_ko) * 2;
                ldsm_x2(bh[nt],  sb + 2 * TILE_B + boff);
                ldsm_x2(bl2[nt], sb + 3 * TILE_B + boff);
            }
            #pragma unroll
            for (int mt = 0; mt < 4; ++mt) {
                uint32_t aoff = (uint32_t)((m_base + mt * 16 + a_r) * PADK
                                           + kof + a_ko) * 2;
                uint32_t ah[4], al[4];
                ldsm_x4(ah, sb + aoff);
                ldsm_x4(al, sb + TILE_B + aoff);
                #pragma unroll
                for (int nt = 0; nt < 4; ++nt) {
                    mma_bf16(acc[mt][nt], ah, bh[nt]);
                    mma_bf16(acc[mt][nt], ah, bl2[nt]);
                    mma_bf16(acc[mt][nt], al, bh[nt]);
                }
            }
        }
    }

    // ---- epilogue: raw fp32 store (mix/bias/norm in post pass) ----
    const int rq = lid >> 2, cq = (lid & 3) * 2;
    #pragma unroll
    for (int mt = 0; mt < 4; ++mt) {
        #pragma unroll
        for (int nt = 0; nt < 4; ++nt) {
            size_t gcol = (size_t)by * 128 + n_base + nt * 8 + cq;
            size_t r0 = (size_t)bm * 128 + m_base + mt * 16 + rq;
            *(float2*)(C + r0 * Ntot + gcol) =
                make_float2(acc[mt][nt][0], acc[mt][nt][1]);
            *(float2*)(C + (r0 + 8) * Ntot + gcol) =
                make_float2(acc[mt][nt][2], acc[mt][nt][3]);
        }
    }
}

// ---------------------------------------------------------------------------
// GCN post: h[b,n,f] = relu( sum_m A[n,m] * P[b,m,f] + bias[f] ), split bf16.
// ---------------------------------------------------------------------------
__global__ void gcn_post_kernel(const float* __restrict__ P,
                                const float* __restrict__ bias,
                                int B, int F)
{
    int f4cnt = F >> 2;
    long long idx = (long long)blockIdx.x * blockDim.x + threadIdx.x;
    if (idx >= (long long)B * f4cnt) return;
    int f4 = (int)(idx % f4cnt);
    long long b = idx / f4cnt;
    float mat[16];
    #pragma unroll
    for (int i = 0; i < 16; ++i) mat[i] = g_A[i];

    const float4* Pb = (const float4*)P + b * 4 * f4cnt;
    float4 bv = ((const float4*)bias)[f4];
    float4 v[4];
    #pragma unroll
    for (int m = 0; m < 4; ++m) v[m] = Pb[(size_t)m * f4cnt + f4];
    #pragma unroll
    for (int n = 0; n < 4; ++n) {
        float4 r;
        r.x = fmaxf(mat[n*4+0]*v[0].x + mat[n*4+1]*v[1].x + mat[n*4+2]*v[2].x + mat[n*4+3]*v[3].x + bv.x, 0.f);
        r.y = fmaxf(mat[n*4+0]*v[0].y + mat[n*4+1]*v[1].y + mat[n*4+2]*v[2].y + mat[n*4+3]*v[3].y + bv.y, 0.f);
        r.z = fmaxf(mat[n*4+0]*v[0].z + mat[n*4+1]*v[1].z + mat[n*4+2]*v[2].z + mat[n*4+3]*v[3].z + bv.z, 0.f);
        r.w = fmaxf(mat[n*4+0]*v[0].w + mat[n*4+1]*v[1].w + mat[n*4+2]*v[2].w + mat[n*4+3]*v[3].w + bv.w, 0.f);
        store_split4(g_hh, g_hl, ((size_t)(b * 4 + n) * f4cnt + f4) * 4, r);
    }
}

// ---------------------------------------------------------------------------
// SAGE post: P[M, 2N] = [Pl | Pr].  h[b,n,:] =
//   relu( l2norm( Mix.Pl[b,:,:] (row n) + Pr[b,n,:] + bias ) ), split bf16.
// One block per batch; blockDim = N/4.
// ---------------------------------------------------------------------------
__global__ void sage_post_kernel(const float* __restrict__ P,
                                 const float* __restrict__ bias, int N)
{
    __shared__ float red[4][4];
    const int b = blockIdx.x, tid = threadIdx.x;
    const int wid = tid >> 5, lane = tid & 31;
    const int nw = blockDim.x >> 5;
    float mat[16];
    #pragma unroll
    for (int i = 0; i < 16; ++i) mat[i] = g_M[i];

    const float* Pb = P + (size_t)b * 4 * (2 * N);
    const int f = tid * 4;
    float4 pl[4];
    #pragma unroll
    for (int m = 0; m < 4; ++m)
        pl[m] = *(const float4*)(Pb + (size_t)m * 2 * N + f);
    float4 bv = *(const float4*)(bias + f);

    float4 y[4];
    float ss[4];
    #pragma unroll
    for (int n = 0; n < 4; ++n) {
        float4 pr = *(const float4*)(Pb + (size_t)n * 2 * N + N + f);
        float4 r;
        r.x = mat[n*4+0]*pl[0].x + mat[n*4+1]*pl[1].x + mat[n*4+2]*pl[2].x + mat[n*4+3]*pl[3].x + pr.x + bv.x;
        r.y = mat[n*4+0]*pl[0].y + mat[n*4+1]*pl[1].y + mat[n*4+2]*pl[2].y + mat[n*4+3]*pl[3].y + pr.y + bv.y;
        r.z = mat[n*4+0]*pl[0].z + mat[n*4+1]*pl[1].z + mat[n*4+2]*pl[2].z + mat[n*4+3]*pl[3].z + pr.z + bv.z;
        r.w = mat[n*4+0]*pl[0].w + mat[n*4+1]*pl[1].w + mat[n*4+2]*pl[2].w + mat[n*4+3]*pl[3].w + pr.w + bv.w;
        y[n] = r;
        ss[n] = r.x * r.x + r.y * r.y + r.z * r.z + r.w * r.w;
    }
    #pragma unroll
    for (int n = 0; n < 4; ++n)
        #pragma unroll
        for (int off = 16; off > 0; off >>= 1)
            ss[n] += __shfl_xor_sync(0xffffffffu, ss[n], off);
    if (lane == 0) {
        #pragma unroll
        for (int n = 0; n < 4; ++n) red[n][wid] = ss[n];
    }
    __syncthreads();
    float inv[4];
    #pragma unroll
    for (int n = 0; n < 4; ++n) {
        float t = 0.f;
        for (int w = 0; w < nw; ++w) t += red[n][w];
        inv[n] = 1.f / fmaxf(sqrtf(t), 1e-12f);
    }
    #pragma unroll
    for (int n = 0; n < 4; ++n) {
        float4 o;
        o.x = fmaxf(y[n].x * inv[n], 0.f);
        o.y = fmaxf(y[n].y * inv[n], 0.f);
        o.z = fmaxf(y[n].z * inv[n], 0.f);
        o.w = fmaxf(y[n].w * inv[n], 0.f);
        store_split4(g_hh, g_hl, (size_t)(b * 4 + n) * N + f, o);
    }
}

// ---------------------------------------------------------------------------
// FC [B,1024] @ Wfc[1024,10] + bfc, softmax. One warp per batch row.
// Input h read as hi+lo bf16 pairs.
// ---------------------------------------------------------------------------
__global__ void fc_softmax_kernel(const float* __restrict__ Wfc,
                                  const float* __restrict__ bfc,
                                  float* __restrict__ out, int B)
{
    long long warp = ((long long)blockIdx.x * blockDim.x + threadIdx.x) >> 5;
    int lane = threadIdx.x & 31;
    if (warp >= B) return;
    const size_t base = (size_t)warp * 1024;
    float acc[10];
    #pragma unroll
    for (int o = 0; o < 10; ++o) acc[o] = 0.f;
    for (int k = lane; k < 1024; k += 32) {
        float hv = __bfloat162float(g_hh[base + k]) +
                   __bfloat162float(g_hl[base + k]);
        const float* w = Wfc + (size_t)k * 10;
        #pragma unroll
        for (int o = 0; o < 10; ++o) acc[o] += hv * w[o];
    }
    #pragma unroll
    for (int o = 0; o < 10; ++o)
        #pragma unroll
        for (int off = 16; off > 0; off >>= 1)
            acc[o] += __shfl_xor_sync(0xffffffffu, acc[o], off);
    if (lane == 0) {
        float logit[10], m = -1e30f;
        #pragma unroll
        for (int o = 0; o < 10; ++o) {
            logit[o] = acc[o] + bfc[o];
            m = fmaxf(m, logit[o]);
        }
        float s = 0.f;
        #pragma unroll
        for (int o = 0; o < 10; ++o) { logit[o] = expf(logit[o] - m); s += logit[o]; }
        float invs = 1.f / s;
        float* orow = out + (size_t)warp * 10;
        #pragma unroll
        for (int o = 0; o < 10; ++o) orow[o] = logit[o] * invs;
    }
}

// ---------------------------------------------------------------------------
extern "C" void kernel_launch(void* const* d_in, const int* in_sizes, int n_in,
                              void* d_out, int out_size)
{
    const float* x   = (const float*)d_in[0];
    const void*  ei  = d_in[1];
    const float* W1  = (const float*)d_in[2];
    const float* b1  = (const float*)d_in[3];
    const float* Wl2 = (const float*)d_in[4];
    const float* bl2 = (const float*)d_in[5];
    const float* Wr2 = (const float*)d_in[6];
    const float* Wl3 = (const float*)d_in[7];
    const float* bl3 = (const float*)d_in[8];
    const float* Wr3 = (const float*)d_in[9];
    const float* Wl4 = (const float*)d_in[10];
    const float* bl4 = (const float*)d_in[11];
    const float* Wr4 = (const float*)d_in[12];
    const float* Wfc = (const float*)d_in[13];
    const float* bfc = (const float*)d_in[14];

    const int B = in_sizes[0] / (4 * 64);
    const int E = in_sizes[1] / 2;
    const long long M = (long long)B * 4;

    float* bufA;
    __nv_bfloat16 *hh, *hl;
    cudaGetSymbolAddress((void**)&bufA, g_bufA);
    cudaGetSymbolAddress((void**)&hh, g_hh);
    cudaGetSymbolAddress((void**)&hl, g_hl);

    cudaFuncSetAttribute(gemm_tc_kernel,
                         cudaFuncAttributeMaxDynamicSharedMemorySize, SMEM_BYTES);

    build_graph_kernel<<<1, 32>>>(ei, E);

    // weight prep: N-concat layout [Ntot][K0], offsets in bf16 elements
    const size_t OW1 = 0;                       // [1024][64]
    const size_t OW2 = 65536;                   // [1024][1024] = [Wl2|Wr2]
    const size_t OW3 = OW2 + 1048576;           // [512][512]  = [Wl3|Wr3]
    const size_t OW4 = OW3 + 262144;            // [512][256]  = [Wl4|Wr4]
    prep_w_kernel<<<(64   * 1024 + 255) / 256, 256>>>(W1,  64,   1024, OW1);
    prep_w_kernel<<<(1024 * 512  + 255) / 256, 256>>>(Wl2, 1024, 512,  OW2);
    prep_w_kernel<<<(1024 * 512  + 255) / 256, 256>>>(Wr2, 1024, 512,  OW2 + (size_t)512 * 1024);
    prep_w_kernel<<<(512  * 256  + 255) / 256, 256>>>(Wl3, 512,  256,  OW3);
    prep_w_kernel<<<(512  * 256  + 255) / 256, 256>>>(Wr3, 512,  256,  OW3 + (size_t)256 * 512);
    prep_w_kernel<<<(256  * 256  + 255) / 256, 256>>>(Wl4, 256,  256,  OW4);
    prep_w_kernel<<<(256  * 256  + 255) / 256, 256>>>(Wr4, 256,  256,  OW4 + (size_t)256 * 256);

    const unsigned gm = (unsigned)(M / 128);

    // x -> bf16 hi/lo
    split_x_kernel<<<(unsigned)((M * 16 + 255) / 256), 256>>>(x, M * 16);
    // L1: P1 = x @ W1 [M,1024];  h1 = relu(Mix.P1 + b1) (split bf16)
    gemm_tc_kernel<<<dim3(8, gm), 256, SMEM_BYTES>>>(hh, hl, OW1, bufA, 64, 1024);
    gcn_post_kernel<<<(unsigned)(((long long)B * 256 + 255) / 256), 256>>>(
        bufA, b1, B, 1024);
    // L2: P2 = h1 @ [Wl2|Wr2] [M,1024];  h2 = sage_post(P2) [M,512]
    gemm_tc_kernel<<<dim3(8, gm), 256, SMEM_BYTES>>>(hh, hl, OW2, bufA, 1024, 1024);
    sage_post_kernel<<<B, 128>>>(bufA, bl2, 512);
    // L3: P3 = h2 @ [Wl3|Wr3] [M,512];  h3 [M,256]
    gemm_tc_kernel<<<dim3(4, gm), 256, SMEM_BYTES>>>(hh, hl, OW3, bufA, 512, 512);
    sage_post_kernel<<<B, 64>>>(bufA, bl3, 256);
    // L4: P4 = h3 @ [Wl4|Wr4] [M,512];  h4 [M,256]
    gemm_tc_kernel<<<dim3(4, gm), 256, SMEM_BYTES>>>(hh, hl, OW4, bufA, 256, 512);
    sage_post_kernel<<<B, 64>>>(bufA, bl4, 256);
    // FC + softmax
    fc_softmax_kernel<<<(unsigned)((B * 32 + 255) / 256), 256>>>(
        Wfc, bfc, (float*)d_out, B);
}

// round 7
// speedup vs baseline: 4.2932x; 1.5911x over previous
#include <cuda_runtime.h>
#include <cuda_fp16.h>
#include <math.h>
#include <stdint.h>

// ===========================================================================
// GNN over fixed 4-node graph, B=32768 (M = 4B = 131072 rows).
// GEMMs: mma.sync fp16, 2-MMA split: A_h @ (W_h + W_l), fp32 accumulate.
//   (dropped term al*w ~ 2.8e-4 theoretical, ~1e-5 measured after network)
// Activations stored as single fp16 array (written by fused post-passes).
// Graph mixing (4x4) fused into post-passes (mix-after-GEMM identity).
// ===========================================================================

#define MAXB 32768
#define PADK 72                 // 64 + 8 pad (fp16) -> conflict-free ldmatrix
#define TILE_B (128 * PADK * 2) // 18432 bytes per 128x64 fp16 tile
#define STAGE_B (3 * TILE_B)    // A, WH, WL
#define SMEM_BYTES (2 * STAGE_B)

__device__ float g_A[16];   // GCN normalized adjacency (4x4)
__device__ float g_M[16];   // SAGE mean-aggregation matrix (4x4)
__device__ float g_bufA[(size_t)MAXB * 4 * 1024];                 // fp32 GEMM out
__device__ __align__(16) __half g_hf[(size_t)MAXB * 4 * 1024];    // fp16 acts
__device__ __align__(16) __half g_wt_hi[1507328];
__device__ __align__(16) __half g_wt_lo[1507328];

// ---------------------------------------------------------------------------
__device__ __forceinline__ uint32_t smem_u32(const void* p) {
    uint32_t a;
    asm("{ .reg .u64 t; cvta.to.shared.u64 t, %1; cvt.u32.u64 %0, t; }"
        : "=r"(a) : "l"(p));
    return a;
}
__device__ __forceinline__ void ldsm_x4(uint32_t (&r)[4], uint32_t addr) {
    asm volatile("ldmatrix.sync.aligned.m8n8.x4.shared.b16 {%0,%1,%2,%3}, [%4];"
                 : "=r"(r[0]), "=r"(r[1]), "=r"(r[2]), "=r"(r[3]) : "r"(addr));
}
__device__ __forceinline__ void ldsm_x2(uint32_t (&r)[2], uint32_t addr) {
    asm volatile("ldmatrix.sync.aligned.m8n8.x2.shared.b16 {%0,%1}, [%2];"
                 : "=r"(r[0]), "=r"(r[1]) : "r"(addr));
}
__device__ __forceinline__ void mma_f16(float (&d)[4], const uint32_t (&a)[4],
                                        const uint32_t (&b)[2]) {
    asm volatile(
        "mma.sync.aligned.m16n8k16.row.col.f32.f16.f16.f32 "
        "{%0,%1,%2,%3}, {%4,%5,%6,%7}, {%8,%9}, {%0,%1,%2,%3};"
        : "+f"(d[0]), "+f"(d[1]), "+f"(d[2]), "+f"(d[3])
        : "r"(a[0]), "r"(a[1]), "r"(a[2]), "r"(a[3]), "r"(b[0]), "r"(b[1]));
}
__device__ __forceinline__ void cp_async16(uint32_t dst, const void* src) {
    asm volatile("cp.async.cg.shared.global [%0], [%1], 16;"
                 :: "r"(dst), "l"(src));
}
#define CP_COMMIT() asm volatile("cp.async.commit_group;" ::: "memory")
#define CP_WAIT0()  asm volatile("cp.async.wait_group 0;" ::: "memory")

__device__ __forceinline__ uint32_t h2pack(float a, float b) {
    __half2 h = __floats2half2_rn(a, b);
    return *(uint32_t*)&h;
}
// write 4 consecutive fp16 at element offset e
__device__ __forceinline__ void store_h4(__half* H, size_t e, float4 v) {
    *(uint2*)(H + e) = make_uint2(h2pack(v.x, v.y), h2pack(v.z, v.w));
}

// ---------------------------------------------------------------------------
// Build 4x4 mixing matrices from edge_index (dtype-adaptive int32/int64).
// ---------------------------------------------------------------------------
__global__ void build_graph_kernel(const void* __restrict__ ei_raw, int E)
{
    if (threadIdx.x != 0 || blockIdx.x != 0) return;
    const long long* e64 = (const long long*)ei_raw;
    const int*       e32 = (const int*)ei_raw;
    bool is64 = true;
    for (int e = 0; e < E; ++e) {
        long long v = e64[e];
        if (v < 0 || v >= 4) { is64 = false; break; }
    }
    int src[64], dst[64];
    for (int e = 0; e < E; ++e) {
        if (is64) { src[e] = (int)e64[e]; dst[e] = (int)e64[E + e]; }
        else      { src[e] = e32[e];      dst[e] = e32[E + e]; }
    }
    float degG[4] = {1.f, 1.f, 1.f, 1.f};
    float cntS[4] = {0.f, 0.f, 0.f, 0.f};
    for (int e = 0; e < E; ++e) { degG[dst[e]] += 1.f; cntS[dst[e]] += 1.f; }
    float dinv[4];
    #pragma unroll
    for (int n = 0; n < 4; ++n) dinv[n] = rsqrtf(degG[n]);
    float A[16], M[16];
    #pragma unroll
    for (int i = 0; i < 16; ++i) { A[i] = 0.f; M[i] = 0.f; }
    for (int e = 0; e < E; ++e) {
        int s = src[e], d = dst[e];
        A[d * 4 + s] += dinv[s] * dinv[d];
        M[d * 4 + s] += 1.f / fmaxf(cntS[d], 1.f);
    }
    #pragma unroll
    for (int n = 0; n < 4; ++n) A[n * 4 + n] += dinv[n] * dinv[n];
    #pragma unroll
    for (int i = 0; i < 16; ++i) { g_A[i] = A[i]; g_M[i] = M[i]; }
}

// ---------------------------------------------------------------------------
// Weight prep: split fp32 W[K0,N] (row-major) into fp16 hi/lo stored [N][K0].
// ---------------------------------------------------------------------------
__global__ void prep_w_kernel(const float* __restrict__ W, int K0, int N,
                              size_t dst_off)
{
    long long idx = (long long)blockIdx.x * 256 + threadIdx.x;
    if (idx >= (long long)K0 * N) return;
    int k = (int)(idx / N), n = (int)(idx % N);
    float v = W[idx];
    __half h = __float2half_rn(v);
    __half l = __float2half_rn(v - __half2float(h));
    size_t o = dst_off + (size_t)n * K0 + k;
    g_wt_hi[o] = h;
    g_wt_lo[o] = l;
}

// ---------------------------------------------------------------------------
// Convert fp32 X[n] to fp16 (network input).
// ---------------------------------------------------------------------------
__global__ void split_x_kernel(const float* __restrict__ X, long long n4)
{
    long long i = (long long)blockIdx.x * 256 + threadIdx.x;
    if (i >= n4) return;
    float4 v = ((const float4*)X)[i];
    store_h4(g_hf, (size_t)i * 4, v);
}

// ---------------------------------------------------------------------------
// fp16 2-MMA tensor-core GEMM: C[M,Ntot] = A[M,K0] @ (Wh+Wl)[K0,Ntot]
// grid = (Ntot/128, M/128); 256 threads (8 warps 2x4); warp tile 64x32.
// cp.async double-buffered (A, Wh, Wl); one __syncthreads per k-chunk.
// ---------------------------------------------------------------------------
__global__ __launch_bounds__(256, 2)
void gemm_tc_kernel(const __half* __restrict__ Ain,
                    size_t w_off, float* __restrict__ C, int K0, int Ntot)
{
    extern __shared__ char smem[];
    const uint32_t sbase = smem_u32(smem);
    const int tid = threadIdx.x, wid = tid >> 5, lid = tid & 31;
    const int by = blockIdx.x, bm = blockIdx.y;
    const int warp_m = wid & 1, warp_n = wid >> 1;
    const int m_base = warp_m * 64, n_base = warp_n * 32;

    float acc[4][4][4];
    #pragma unroll
    for (int mt = 0; mt < 4; ++mt)
        #pragma unroll
        for (int nt = 0; nt < 4; ++nt)
            #pragma unroll
            for (int i = 0; i < 4; ++i) acc[mt][nt][i] = 0.f;

    const int a_r  = lid & 15;
    const int a_ko = (lid >> 4) << 3;
    const int b_r  = lid & 7;
    const int b_ko = (lid & 8);

    const int KC = K0 >> 6;
    const __half* Ab  = Ain + (size_t)bm * 128 * K0;
    const __half* WHb = g_wt_hi + w_off + (size_t)by * 128 * K0;
    const __half* WLb = g_wt_lo + w_off + (size_t)by * 128 * K0;

    auto prefetch = [&](int kc, int st) {
        uint32_t sb = sbase + st * STAGE_B;
        #pragma unroll
        for (int i = 0; i < 4; ++i) {
            int c = tid + i * 256, r = c >> 3, q = c & 7;
            uint32_t so = (uint32_t)(r * PADK + q * 8) * 2;
            size_t go = (size_t)r * K0 + (size_t)kc * 64 + q * 8;
            cp_async16(sb + so,              Ab  + go);
            cp_async16(sb + TILE_B + so,     WHb + go);
            cp_async16(sb + 2 * TILE_B + so, WLb + go);
        }
        CP_COMMIT();
    };

    prefetch(0, 0);

    for (int kc = 0; kc < KC; ++kc) {
        CP_WAIT0();
        __syncthreads();          // tile kc visible; all MMA(kc-1) complete
        if (kc + 1 < KC) prefetch(kc + 1, (kc + 1) & 1);

        const uint32_t sb = sbase + (kc & 1) * STAGE_B;
        #pragma unroll
        for (int ks = 0; ks < 4; ++ks) {
            const int kof = ks * 16;
            uint32_t bh[4][2], bl2[4][2];
            #pragma unroll
            for (int nt = 0; nt < 4; ++nt) {
                uint32_t boff = (uint32_t)((n_base + nt * 8 + b_r) * PADK
                                           + kof + b_ko) * 2;
                ldsm_x2(bh[nt],  sb + TILE_B + boff);
                ldsm_x2(bl2[nt], sb + 2 * TILE_B + boff);
            }
            #pragma unroll
            for (int mt = 0; mt < 4; ++mt) {
                uint32_t aoff = (uint32_t)((m_base + mt * 16 + a_r) * PADK
                                           + kof + a_ko) * 2;
                uint32_t ah[4];
                ldsm_x4(ah, sb + aoff);
                #pragma unroll
                for (int nt = 0; nt < 4; ++nt) {
                    mma_f16(acc[mt][nt], ah, bh[nt]);
                    mma_f16(acc[mt][nt], ah, bl2[nt]);
                }
            }
        }
    }

    // ---- epilogue: raw fp32 store (mix/bias/norm in post pass) ----
    const int rq = lid >> 2, cq = (lid & 3) * 2;
    #pragma unroll
    for (int mt = 0; mt < 4; ++mt) {
        #pragma unroll
        for (int nt = 0; nt < 4; ++nt) {
            size_t gcol = (size_t)by * 128 + n_base + nt * 8 + cq;
            size_t r0 = (size_t)bm * 128 + m_base + mt * 16 + rq;
            *(float2*)(C + r0 * Ntot + gcol) =
                make_float2(acc[mt][nt][0], acc[mt][nt][1]);
            *(float2*)(C + (r0 + 8) * Ntot + gcol) =
                make_float2(acc[mt][nt][2], acc[mt][nt][3]);
        }
    }
}

// ---------------------------------------------------------------------------
// GCN post: h[b,n,f] = relu( sum_m A[n,m] * P[b,m,f] + bias[f] ), fp16 out.
// ---------------------------------------------------------------------------
__global__ void gcn_post_kernel(const float* __restrict__ P,
                                const float* __restrict__ bias,
                                int B, int F)
{
    int f4cnt = F >> 2;
    long long idx = (long long)blockIdx.x * blockDim.x + threadIdx.x;
    if (idx >= (long long)B * f4cnt) return;
    int f4 = (int)(idx % f4cnt);
    long long b = idx / f4cnt;
    float mat[16];
    #pragma unroll
    for (int i = 0; i < 16; ++i) mat[i] = g_A[i];

    const float4* Pb = (const float4*)P + b * 4 * f4cnt;
    float4 bv = ((const float4*)bias)[f4];
    float4 v[4];
    #pragma unroll
    for (int m = 0; m < 4; ++m) v[m] = Pb[(size_t)m * f4cnt + f4];
    #pragma unroll
    for (int n = 0; n < 4; ++n) {
        float4 r;
        r.x = fmaxf(mat[n*4+0]*v[0].x + mat[n*4+1]*v[1].x + mat[n*4+2]*v[2].x + mat[n*4+3]*v[3].x + bv.x, 0.f);
        r.y = fmaxf(mat[n*4+0]*v[0].y + mat[n*4+1]*v[1].y + mat[n*4+2]*v[2].y + mat[n*4+3]*v[3].y + bv.y, 0.f);
        r.z = fmaxf(mat[n*4+0]*v[0].z + mat[n*4+1]*v[1].z + mat[n*4+2]*v[2].z + mat[n*4+3]*v[3].z + bv.z, 0.f);
        r.w = fmaxf(mat[n*4+0]*v[0].w + mat[n*4+1]*v[1].w + mat[n*4+2]*v[2].w + mat[n*4+3]*v[3].w + bv.w, 0.f);
        store_h4(g_hf, ((size_t)(b * 4 + n) * f4cnt + f4) * 4, r);
    }
}

// ---------------------------------------------------------------------------
// SAGE post: P[M, 2N] = [Pl | Pr].  h[b,n,:] =
//   relu( l2norm( Mix.Pl[b,:,:] (row n) + Pr[b,n,:] + bias ) ), fp16 out.
// One block per batch; blockDim = N/4.
// ---------------------------------------------------------------------------
__global__ void sage_post_kernel(const float* __restrict__ P,
                                 const float* __restrict__ bias, int N)
{
    __shared__ float red[4][4];
    const int b = blockIdx.x, tid = threadIdx.x;
    const int wid = tid >> 5, lane = tid & 31;
    const int nw = blockDim.x >> 5;
    float mat[16];
    #pragma unroll
    for (int i = 0; i < 16; ++i) mat[i] = g_M[i];

    const float* Pb = P + (size_t)b * 4 * (2 * N);
    const int f = tid * 4;
    float4 pl[4];
    #pragma unroll
    for (int m = 0; m < 4; ++m)
        pl[m] = *(const float4*)(Pb + (size_t)m * 2 * N + f);
    float4 bv = *(const float4*)(bias + f);

    float4 y[4];
    float ss[4];
    #pragma unroll
    for (int n = 0; n < 4; ++n) {
        float4 pr = *(const float4*)(Pb + (size_t)n * 2 * N + N + f);
        float4 r;
        r.x = mat[n*4+0]*pl[0].x + mat[n*4+1]*pl[1].x + mat[n*4+2]*pl[2].x + mat[n*4+3]*pl[3].x + pr.x + bv.x;
        r.y = mat[n*4+0]*pl[0].y + mat[n*4+1]*pl[1].y + mat[n*4+2]*pl[2].y + mat[n*4+3]*pl[3].y + pr.y + bv.y;
        r.z = mat[n*4+0]*pl[0].z + mat[n*4+1]*pl[1].z + mat[n*4+2]*pl[2].z + mat[n*4+3]*pl[3].z + pr.z + bv.z;
        r.w = mat[n*4+0]*pl[0].w + mat[n*4+1]*pl[1].w + mat[n*4+2]*pl[2].w + mat[n*4+3]*pl[3].w + pr.w + bv.w;
        y[n] = r;
        ss[n] = r.x * r.x + r.y * r.y + r.z * r.z + r.w * r.w;
    }
    #pragma unroll
    for (int n = 0; n < 4; ++n)
        #pragma unroll
        for (int off = 16; off > 0; off >>= 1)
            ss[n] += __shfl_xor_sync(0xffffffffu, ss[n], off);
    if (lane == 0) {
        #pragma unroll
        for (int n = 0; n < 4; ++n) red[n][wid] = ss[n];
    }
    __syncthreads();
    float inv[4];
    #pragma unroll
    for (int n = 0; n < 4; ++n) {
        float t = 0.f;
        for (int w = 0; w < nw; ++w) t += red[n][w];
        inv[n] = 1.f / fmaxf(sqrtf(t), 1e-12f);
    }
    #pragma unroll
    for (int n = 0; n < 4; ++n) {
        float4 o;
        o.x = fmaxf(y[n].x * inv[n], 0.f);
        o.y = fmaxf(y[n].y * inv[n], 0.f);
        o.z = fmaxf(y[n].z * inv[n], 0.f);
        o.w = fmaxf(y[n].w * inv[n], 0.f);
        store_h4(g_hf, (size_t)(b * 4 + n) * N + f, o);
    }
}

// ---------------------------------------------------------------------------
// FC [B,1024] @ Wfc[1024,10] + bfc, softmax. One warp per batch row.
// ---------------------------------------------------------------------------
__global__ void fc_softmax_kernel(const float* __restrict__ Wfc,
                                  const float* __restrict__ bfc,
                                  float* __restrict__ out, int B)
{
    long long warp = ((long long)blockIdx.x * blockDim.x + threadIdx.x) >> 5;
    int lane = threadIdx.x & 31;
    if (warp >= B) return;
    const size_t base = (size_t)warp * 1024;
    float acc[10];
    #pragma unroll
    for (int o = 0; o < 10; ++o) acc[o] = 0.f;
    for (int k = lane; k < 1024; k += 32) {
        float hv = __half2float(g_hf[base + k]);
        const float* w = Wfc + (size_t)k * 10;
        #pragma unroll
        for (int o = 0; o < 10; ++o) acc[o] += hv * w[o];
    }
    #pragma unroll
    for (int o = 0; o < 10; ++o)
        #pragma unroll
        for (int off = 16; off > 0; off >>= 1)
            acc[o] += __shfl_xor_sync(0xffffffffu, acc[o], off);
    if (lane == 0) {
        float logit[10], m = -1e30f;
        #pragma unroll
        for (int o = 0; o < 10; ++o) {
            logit[o] = acc[o] + bfc[o];
            m = fmaxf(m, logit[o]);
        }
        float s = 0.f;
        #pragma unroll
        for (int o = 0; o < 10; ++o) { logit[o] = expf(logit[o] - m); s += logit[o]; }
        float invs = 1.f / s;
        float* orow = out + (size_t)warp * 10;
        #pragma unroll
        for (int o = 0; o < 10; ++o) orow[o] = logit[o] * invs;
    }
}

// ---------------------------------------------------------------------------
extern "C" void kernel_launch(void* const* d_in, const int* in_sizes, int n_in,
                              void* d_out, int out_size)
{
    const float* x   = (const float*)d_in[0];
    const void*  ei  = d_in[1];
    const float* W1  = (const float*)d_in[2];
    const float* b1  = (const float*)d_in[3];
    const float* Wl2 = (const float*)d_in[4];
    const float* bl2 = (const float*)d_in[5];
    const float* Wr2 = (const float*)d_in[6];
    const float* Wl3 = (const float*)d_in[7];
    const float* bl3 = (const float*)d_in[8];
    const float* Wr3 = (const float*)d_in[9];
    const float* Wl4 = (const float*)d_in[10];
    const float* bl4 = (const float*)d_in[11];
    const float* Wr4 = (const float*)d_in[12];
    const float* Wfc = (const float*)d_in[13];
    const float* bfc = (const float*)d_in[14];

    const int B = in_sizes[0] / (4 * 64);
    const int E = in_sizes[1] / 2;
    const long long M = (long long)B * 4;

    float* bufA;
    __half* hf;
    cudaGetSymbolAddress((void**)&bufA, g_bufA);
    cudaGetSymbolAddress((void**)&hf, g_hf);

    cudaFuncSetAttribute(gemm_tc_kernel,
                         cudaFuncAttributeMaxDynamicSharedMemorySize, SMEM_BYTES);

    build_graph_kernel<<<1, 32>>>(ei, E);

    // weight prep: N-concat layout [Ntot][K0], offsets in fp16 elements
    const size_t OW1 = 0;                       // [1024][64]
    const size_t OW2 = 65536;                   // [1024][1024] = [Wl2|Wr2]
    const size_t OW3 = OW2 + 1048576;           // [512][512]  = [Wl3|Wr3]
    const size_t OW4 = OW3 + 262144;            // [512][256]  = [Wl4|Wr4]
    prep_w_kernel<<<(64   * 1024 + 255) / 256, 256>>>(W1,  64,   1024, OW1);
    prep_w_kernel<<<(1024 * 512  + 255) / 256, 256>>>(Wl2, 1024, 512,  OW2);
    prep_w_kernel<<<(1024 * 512  + 255) / 256, 256>>>(Wr2, 1024, 512,  OW2 + (size_t)512 * 1024);
    prep_w_kernel<<<(512  * 256  + 255) / 256, 256>>>(Wl3, 512,  256,  OW3);
    prep_w_kernel<<<(512  * 256  + 255) / 256, 256>>>(Wr3, 512,  256,  OW3 + (size_t)256 * 512);
    prep_w_kernel<<<(256  * 256  + 255) / 256, 256>>>(Wl4, 256,  256,  OW4);
    prep_w_kernel<<<(256  * 256  + 255) / 256, 256>>>(Wr4, 256,  256,  OW4 + (size_t)256 * 256);

    const unsigned gm = (unsigned)(M / 128);

    // x -> fp16
    split_x_kernel<<<(unsigned)((M * 16 + 255) / 256), 256>>>(x, M * 16);
    // L1: P1 = x @ W1 [M,1024];  h1 = relu(Mix.P1 + b1) (fp16)
    gemm_tc_kernel<<<dim3(8, gm), 256, SMEM_BYTES>>>(hf, OW1, bufA, 64, 1024);
    gcn_post_kernel<<<(unsigned)(((long long)B * 256 + 255) / 256), 256>>>(
        bufA, b1, B, 1024);
    // L2: P2 = h1 @ [Wl2|Wr2] [M,1024];  h2 = sage_post(P2) [M,512]
    gemm_tc_kernel<<<dim3(8, gm), 256, SMEM_BYTES>>>(hf, OW2, bufA, 1024, 1024);
    sage_post_kernel<<<B, 128>>>(bufA, bl2, 512);
    // L3: P3 = h2 @ [Wl3|Wr3] [M,512];  h3 [M,256]
    gemm_tc_kernel<<<dim3(4, gm), 256, SMEM_BYTES>>>(hf, OW3, bufA, 512, 512);
    sage_post_kernel<<<B, 64>>>(bufA, bl3, 256);
    // L4: P4 = h3 @ [Wl4|Wr4] [M,512];  h4 [M,256]
    gemm_tc_kernel<<<dim3(4, gm), 256, SMEM_BYTES>>>(hf, OW4, bufA, 256, 512);
    sage_post_kernel<<<B, 64>>>(bufA, bl4, 256);
    // FC + softmax
    fc_softmax_kernel<<<(unsigned)((B * 32 + 255) / 256), 256>>>(
        Wfc, bfc, (float*)d_out, B);
}

// round 8
// speedup vs baseline: 6.7216x; 1.5656x over previous
#include <cuda_runtime.h>
#include <cuda_fp16.h>
#include <math.h>
#include <stdint.h>

// ===========================================================================
// GNN over fixed 4-node graph, B=32768 (M = 4B = 131072 rows).
// GEMMs: single mma.sync fp16 x fp16 -> fp32 accum (error budget measured:
// 2-MMA split gave 2.4e-5; independent W rounding adds in quadrature).
// Intermediates P stored fp16. Activations fp16. Mixing (4x4) in post-passes.
// ===========================================================================

#define MAXB 32768
#define PADK 72                 // 64 + 8 pad (fp16) -> conflict-free ldmatrix
#define TILE_B (128 * PADK * 2) // 18432 bytes per 128x64 fp16 tile
#define STAGE_B (2 * TILE_B)    // A, W
#define SMEM_BYTES (2 * STAGE_B)

__device__ float g_A[16];   // GCN normalized adjacency (4x4)
__device__ float g_M[16];   // SAGE mean-aggregation matrix (4x4)
__device__ __align__(16) __half g_Pf[(size_t)MAXB * 4 * 1024];    // fp16 GEMM out
__device__ __align__(16) __half g_hf[(size_t)MAXB * 4 * 1024];    // fp16 acts
__device__ __align__(16) __half g_wt[1507328];                    // fp16 weights

// ---------------------------------------------------------------------------
__device__ __forceinline__ uint32_t smem_u32(const void* p) {
    uint32_t a;
    asm("{ .reg .u64 t; cvta.to.shared.u64 t, %1; cvt.u32.u64 %0, t; }"
        : "=r"(a) : "l"(p));
    return a;
}
__device__ __forceinline__ void ldsm_x4(uint32_t (&r)[4], uint32_t addr) {
    asm volatile("ldmatrix.sync.aligned.m8n8.x4.shared.b16 {%0,%1,%2,%3}, [%4];"
                 : "=r"(r[0]), "=r"(r[1]), "=r"(r[2]), "=r"(r[3]) : "r"(addr));
}
__device__ __forceinline__ void ldsm_x2(uint32_t (&r)[2], uint32_t addr) {
    asm volatile("ldmatrix.sync.aligned.m8n8.x2.shared.b16 {%0,%1}, [%2];"
                 : "=r"(r[0]), "=r"(r[1]) : "r"(addr));
}
__device__ __forceinline__ void mma_f16(float (&d)[4], const uint32_t (&a)[4],
                                        const uint32_t (&b)[2]) {
    asm volatile(
        "mma.sync.aligned.m16n8k16.row.col.f32.f16.f16.f32 "
        "{%0,%1,%2,%3}, {%4,%5,%6,%7}, {%8,%9}, {%0,%1,%2,%3};"
        : "+f"(d[0]), "+f"(d[1]), "+f"(d[2]), "+f"(d[3])
        : "r"(a[0]), "r"(a[1]), "r"(a[2]), "r"(a[3]), "r"(b[0]), "r"(b[1]));
}
__device__ __forceinline__ void cp_async16(uint32_t dst, const void* src) {
    asm volatile("cp.async.cg.shared.global [%0], [%1], 16;"
                 :: "r"(dst), "l"(src));
}
#define CP_COMMIT() asm volatile("cp.async.commit_group;" ::: "memory")
#define CP_WAIT0()  asm volatile("cp.async.wait_group 0;" ::: "memory")

__device__ __forceinline__ uint32_t h2pack(float a, float b) {
    __half2 h = __floats2half2_rn(a, b);
    return *(uint32_t*)&h;
}
__device__ __forceinline__ void store_h4(__half* H, size_t e, float4 v) {
    *(uint2*)(H + e) = make_uint2(h2pack(v.x, v.y), h2pack(v.z, v.w));
}
// load 4 consecutive fp16 at element offset e as float4
__device__ __forceinline__ float4 load_h4(const __half* H, size_t e) {
    uint2 u = *(const uint2*)(H + e);
    __half2 p0 = *(__half2*)&u.x, p1 = *(__half2*)&u.y;
    float2 a = __half22float2(p0), b = __half22float2(p1);
    return make_float4(a.x, a.y, b.x, b.y);
}

// ---------------------------------------------------------------------------
// Build 4x4 mixing matrices from edge_index (dtype-adaptive int32/int64).
// ---------------------------------------------------------------------------
__global__ void build_graph_kernel(const void* __restrict__ ei_raw, int E)
{
    if (threadIdx.x != 0 || blockIdx.x != 0) return;
    const long long* e64 = (const long long*)ei_raw;
    const int*       e32 = (const int*)ei_raw;
    bool is64 = true;
    for (int e = 0; e < E; ++e) {
        long long v = e64[e];
        if (v < 0 || v >= 4) { is64 = false; break; }
    }
    int src[64], dst[64];
    for (int e = 0; e < E; ++e) {
        if (is64) { src[e] = (int)e64[e]; dst[e] = (int)e64[E + e]; }
        else      { src[e] = e32[e];      dst[e] = e32[E + e]; }
    }
    float degG[4] = {1.f, 1.f, 1.f, 1.f};
    float cntS[4] = {0.f, 0.f, 0.f, 0.f};
    for (int e = 0; e < E; ++e) { degG[dst[e]] += 1.f; cntS[dst[e]] += 1.f; }
    float dinv[4];
    #pragma unroll
    for (int n = 0; n < 4; ++n) dinv[n] = rsqrtf(degG[n]);
    float A[16], M[16];
    #pragma unroll
    for (int i = 0; i < 16; ++i) { A[i] = 0.f; M[i] = 0.f; }
    for (int e = 0; e < E; ++e) {
        int s = src[e], d = dst[e];
        A[d * 4 + s] += dinv[s] * dinv[d];
        M[d * 4 + s] += 1.f / fmaxf(cntS[d], 1.f);
    }
    #pragma unroll
    for (int n = 0; n < 4; ++n) A[n * 4 + n] += dinv[n] * dinv[n];
    #pragma unroll
    for (int i = 0; i < 16; ++i) { g_A[i] = A[i]; g_M[i] = M[i]; }
}

// ---------------------------------------------------------------------------
// Weight prep: fp32 W[K0,N] (row-major) -> fp16 stored [N][K0].
// ---------------------------------------------------------------------------
__global__ void prep_w_kernel(const float* __restrict__ W, int K0, int N,
                              size_t dst_off)
{
    long long idx = (long long)blockIdx.x * 256 + threadIdx.x;
    if (idx >= (long long)K0 * N) return;
    int k = (int)(idx / N), n = (int)(idx % N);
    g_wt[dst_off + (size_t)n * K0 + k] = __float2half_rn(W[idx]);
}

// ---------------------------------------------------------------------------
// Convert fp32 X[n] to fp16 (network input).
// ---------------------------------------------------------------------------
__global__ void split_x_kernel(const float* __restrict__ X, long long n4)
{
    long long i = (long long)blockIdx.x * 256 + threadIdx.x;
    if (i >= n4) return;
    float4 v = ((const float4*)X)[i];
    store_h4(g_hf, (size_t)i * 4, v);
}

// ---------------------------------------------------------------------------
// fp16 tensor-core GEMM: P[M,Ntot] = A[M,K0] @ W[K0,Ntot], fp16 out.
// grid = (Ntot/128, M/128); 256 threads (8 warps 2x4); warp tile 64x32.
// cp.async double-buffered; one __syncthreads per k-chunk.
// ---------------------------------------------------------------------------
__global__ __launch_bounds__(256, 2)
void gemm_tc_kernel(const __half* __restrict__ Ain,
                    size_t w_off, __half* __restrict__ P, int K0, int Ntot)
{
    extern __shared__ char smem[];
    const uint32_t sbase = smem_u32(smem);
    const int tid = threadIdx.x, wid = tid >> 5, lid = tid & 31;
    const int by = blockIdx.x, bm = blockIdx.y;
    const int warp_m = wid & 1, warp_n = wid >> 1;
    const int m_base = warp_m * 64, n_base = warp_n * 32;

    float acc[4][4][4];
    #pragma unroll
    for (int mt = 0; mt < 4; ++mt)
        #pragma unroll
        for (int nt = 0; nt < 4; ++nt)
            #pragma unroll
            for (int i = 0; i < 4; ++i) acc[mt][nt][i] = 0.f;

    const int a_r  = lid & 15;
    const int a_ko = (lid >> 4) << 3;
    const int b_r  = lid & 7;
    const int b_ko = (lid & 8);

    const int KC = K0 >> 6;
    const __half* Ab = Ain + (size_t)bm * 128 * K0;
    const __half* Wb = g_wt + w_off + (size_t)by * 128 * K0;

    auto prefetch = [&](int kc, int st) {
        uint32_t sb = sbase + st * STAGE_B;
        #pragma unroll
        for (int i = 0; i < 4; ++i) {
            int c = tid + i * 256, r = c >> 3, q = c & 7;
            uint32_t so = (uint32_t)(r * PADK + q * 8) * 2;
            size_t go = (size_t)r * K0 + (size_t)kc * 64 + q * 8;
            cp_async16(sb + so,          Ab + go);
            cp_async16(sb + TILE_B + so, Wb + go);
        }
        CP_COMMIT();
    };

    prefetch(0, 0);

    for (int kc = 0; kc < KC; ++kc) {
        CP_WAIT0();
        __syncthreads();          // tile kc visible; all MMA(kc-1) complete
        if (kc + 1 < KC) prefetch(kc + 1, (kc + 1) & 1);

        const uint32_t sb = sbase + (kc & 1) * STAGE_B;
        #pragma unroll
        for (int ks = 0; ks < 4; ++ks) {
            const int kof = ks * 16;
            uint32_t bh[4][2];
            #pragma unroll
            for (int nt = 0; nt < 4; ++nt) {
                uint32_t boff = (uint32_t)((n_base + nt * 8 + b_r) * PADK
                                           + kof + b_ko) * 2;
                ldsm_x2(bh[nt], sb + TILE_B + boff);
            }
            #pragma unroll
            for (int mt = 0; mt < 4; ++mt) {
                uint32_t aoff = (uint32_t)((m_base + mt * 16 + a_r) * PADK
                                           + kof + a_ko) * 2;
                uint32_t ah[4];
                ldsm_x4(ah, sb + aoff);
                #pragma unroll
                for (int nt = 0; nt < 4; ++nt)
                    mma_f16(acc[mt][nt], ah, bh[nt]);
            }
        }
    }

    // ---- epilogue: fp16 packed stores (mix/bias/norm in post pass) ----
    const int rq = lid >> 2, cq = (lid & 3) * 2;
    #pragma unroll
    for (int mt = 0; mt < 4; ++mt) {
        #pragma unroll
        for (int nt = 0; nt < 4; ++nt) {
            size_t gcol = (size_t)by * 128 + n_base + nt * 8 + cq;
            size_t r0 = (size_t)bm * 128 + m_base + mt * 16 + rq;
            *(uint32_t*)(P + r0 * Ntot + gcol) =
                h2pack(acc[mt][nt][0], acc[mt][nt][1]);
            *(uint32_t*)(P + (r0 + 8) * Ntot + gcol) =
                h2pack(acc[mt][nt][2], acc[mt][nt][3]);
        }
    }
}

// ---------------------------------------------------------------------------
// GCN post: h[b,n,f] = relu( sum_m A[n,m] * P[b,m,f] + bias[f] ), fp16 in/out.
// ---------------------------------------------------------------------------
__global__ void gcn_post_kernel(const float* __restrict__ bias, int B, int F)
{
    int f4cnt = F >> 2;
    long long idx = (long long)blockIdx.x * blockDim.x + threadIdx.x;
    if (idx >= (long long)B * f4cnt) return;
    int f4 = (int)(idx % f4cnt);
    long long b = idx / f4cnt;
    float mat[16];
    #pragma unroll
    for (int i = 0; i < 16; ++i) mat[i] = g_A[i];

    float4 bv = ((const float4*)bias)[f4];
    float4 v[4];
    #pragma unroll
    for (int m = 0; m < 4; ++m)
        v[m] = load_h4(g_Pf, ((size_t)(b * 4 + m) * f4cnt + f4) * 4);
    #pragma unroll
    for (int n = 0; n < 4; ++n) {
        float4 r;
        r.x = fmaxf(mat[n*4+0]*v[0].x + mat[n*4+1]*v[1].x + mat[n*4+2]*v[2].x + mat[n*4+3]*v[3].x + bv.x, 0.f);
        r.y = fmaxf(mat[n*4+0]*v[0].y + mat[n*4+1]*v[1].y + mat[n*4+2]*v[2].y + mat[n*4+3]*v[3].y + bv.y, 0.f);
        r.z = fmaxf(mat[n*4+0]*v[0].z + mat[n*4+1]*v[1].z + mat[n*4+2]*v[2].z + mat[n*4+3]*v[3].z + bv.z, 0.f);
        r.w = fmaxf(mat[n*4+0]*v[0].w + mat[n*4+1]*v[1].w + mat[n*4+2]*v[2].w + mat[n*4+3]*v[3].w + bv.w, 0.f);
        store_h4(g_hf, ((size_t)(b * 4 + n) * f4cnt + f4) * 4, r);
    }
}

// ---------------------------------------------------------------------------
// SAGE post: P[M, 2N] = [Pl | Pr], fp16.  h[b,n,:] =
//   relu( l2norm( Mix.Pl[b,:,:] (row n) + Pr[b,n,:] + bias ) ), fp16 out.
// One block per batch; blockDim = N/4.
// ---------------------------------------------------------------------------
__global__ void sage_post_kernel(const float* __restrict__ bias, int N)
{
    __shared__ float red[4][4];
    const int b = blockIdx.x, tid = threadIdx.x;
    const int wid = tid >> 5, lane = tid & 31;
    const int nw = blockDim.x >> 5;
    float mat[16];
    #pragma unroll
    for (int i = 0; i < 16; ++i) mat[i] = g_M[i];

    const size_t Pb = (size_t)b * 4 * (2 * N);
    const int f = tid * 4;
    float4 pl[4];
    #pragma unroll
    for (int m = 0; m < 4; ++m)
        pl[m] = load_h4(g_Pf, Pb + (size_t)m * 2 * N + f);
    float4 bv = *(const float4*)(bias + f);

    float4 y[4];
    float ss[4];
    #pragma unroll
    for (int n = 0; n < 4; ++n) {
        float4 pr = load_h4(g_Pf, Pb + (size_t)n * 2 * N + N + f);
        float4 r;
        r.x = mat[n*4+0]*pl[0].x + mat[n*4+1]*pl[1].x + mat[n*4+2]*pl[2].x + mat[n*4+3]*pl[3].x + pr.x + bv.x;
        r.y = mat[n*4+0]*pl[0].y + mat[n*4+1]*pl[1].y + mat[n*4+2]*pl[2].y + mat[n*4+3]*pl[3].y + pr.y + bv.y;
        r.z = mat[n*4+0]*pl[0].z + mat[n*4+1]*pl[1].z + mat[n*4+2]*pl[2].z + mat[n*4+3]*pl[3].z + pr.z + bv.z;
        r.w = mat[n*4+0]*pl[0].w + mat[n*4+1]*pl[1].w + mat[n*4+2]*pl[2].w + mat[n*4+3]*pl[3].w + pr.w + bv.w;
        y[n] = r;
        ss[n] = r.x * r.x + r.y * r.y + r.z * r.z + r.w * r.w;
    }
    #pragma unroll
    for (int n = 0; n < 4; ++n)
        #pragma unroll
        for (int off = 16; off > 0; off >>= 1)
            ss[n] += __shfl_xor_sync(0xffffffffu, ss[n], off);
    if (lane == 0) {
        #pragma unroll
        for (int n = 0; n < 4; ++n) red[n][wid] = ss[n];
    }
    __syncthreads();
    float inv[4];
    #pragma unroll
    for (int n = 0; n < 4; ++n) {
        float t = 0.f;
        for (int w = 0; w < nw; ++w) t += red[n][w];
        inv[n] = 1.f / fmaxf(sqrtf(t), 1e-12f);
    }
    #pragma unroll
    for (int n = 0; n < 4; ++n) {
        float4 o;
        o.x = fmaxf(y[n].x * inv[n], 0.f);
        o.y = fmaxf(y[n].y * inv[n], 0.f);
        o.z = fmaxf(y[n].z * inv[n], 0.f);
        o.w = fmaxf(y[n].w * inv[n], 0.f);
        store_h4(g_hf, (size_t)(b * 4 + n) * N + f, o);
    }
}

// ---------------------------------------------------------------------------
// FC [B,1024] @ Wfc[1024,10] + bfc, softmax. One warp per batch row.
// ---------------------------------------------------------------------------
__global__ void fc_softmax_kernel(const float* __restrict__ Wfc,
                                  const float* __restrict__ bfc,
                                  float* __restrict__ out, int B)
{
    long long warp = ((long long)blockIdx.x * blockDim.x + threadIdx.x) >> 5;
    int lane = threadIdx.x & 31;
    if (warp >= B) return;
    const size_t base = (size_t)warp * 1024;
    float acc[10];
    #pragma unroll
    for (int o = 0; o < 10; ++o) acc[o] = 0.f;
    for (int k = lane; k < 1024; k += 32) {
        float hv = __half2float(g_hf[base + k]);
        const float* w = Wfc + (size_t)k * 10;
        #pragma unroll
        for (int o = 0; o < 10; ++o) acc[o] += hv * w[o];
    }
    #pragma unroll
    for (int o = 0; o < 10; ++o)
        #pragma unroll
        for (int off = 16; off > 0; off >>= 1)
            acc[o] += __shfl_xor_sync(0xffffffffu, acc[o], off);
    if (lane == 0) {
        float logit[10], m = -1e30f;
        #pragma unroll
        for (int o = 0; o < 10; ++o) {
            logit[o] = acc[o] + bfc[o];
            m = fmaxf(m, logit[o]);
        }
        float s = 0.f;
        #pragma unroll
        for (int o = 0; o < 10; ++o) { logit[o] = expf(logit[o] - m); s += logit[o]; }
        float invs = 1.f / s;
        float* orow = out + (size_t)warp * 10;
        #pragma unroll
        for (int o = 0; o < 10; ++o) orow[o] = logit[o] * invs;
    }
}

// ---------------------------------------------------------------------------
extern "C" void kernel_launch(void* const* d_in, const int* in_sizes, int n_in,
                              void* d_out, int out_size)
{
    const float* x   = (const float*)d_in[0];
    const void*  ei  = d_in[1];
    const float* W1  = (const float*)d_in[2];
    const float* b1  = (const float*)d_in[3];
    const float* Wl2 = (const float*)d_in[4];
    const float* bl2 = (const float*)d_in[5];
    const float* Wr2 = (const float*)d_in[6];
    const float* Wl3 = (const float*)d_in[7];
    const float* bl3 = (const float*)d_in[8];
    const float* Wr3 = (const float*)d_in[9];
    const float* Wl4 = (const float*)d_in[10];
    const float* bl4 = (const float*)d_in[11];
    const float* Wr4 = (const float*)d_in[12];
    const float* Wfc = (const float*)d_in[13];
    const float* bfc = (const float*)d_in[14];

    const int B = in_sizes[0] / (4 * 64);
    const int E = in_sizes[1] / 2;
    const long long M = (long long)B * 4;

    __half *Pf, *hf;
    cudaGetSymbolAddress((void**)&Pf, g_Pf);
    cudaGetSymbolAddress((void**)&hf, g_hf);

    cudaFuncSetAttribute(gemm_tc_kernel,
                         cudaFuncAttributeMaxDynamicSharedMemorySize, SMEM_BYTES);

    build_graph_kernel<<<1, 32>>>(ei, E);

    // weight prep: N-concat layout [Ntot][K0], offsets in fp16 elements
    const size_t OW1 = 0;                       // [1024][64]
    const size_t OW2 = 65536;                   // [1024][1024] = [Wl2|Wr2]
    const size_t OW3 = OW2 + 1048576;           // [512][512]  = [Wl3|Wr3]
    const size_t OW4 = OW3 + 262144;            // [512][256]  = [Wl4|Wr4]
    prep_w_kernel<<<(64   * 1024 + 255) / 256, 256>>>(W1,  64,   1024, OW1);
    prep_w_kernel<<<(1024 * 512  + 255) / 256, 256>>>(Wl2, 1024, 512,  OW2);
    prep_w_kernel<<<(1024 * 512  + 255) / 256, 256>>>(Wr2, 1024, 512,  OW2 + (size_t)512 * 1024);
    prep_w_kernel<<<(512  * 256  + 255) / 256, 256>>>(Wl3, 512,  256,  OW3);
    prep_w_kernel<<<(512  * 256  + 255) / 256, 256>>>(Wr3, 512,  256,  OW3 + (size_t)256 * 512);
    prep_w_kernel<<<(256  * 256  + 255) / 256, 256>>>(Wl4, 256,  256,  OW4);
    prep_w_kernel<<<(256  * 256  + 255) / 256, 256>>>(Wr4, 256,  256,  OW4 + (size_t)256 * 256);

    const unsigned gm = (unsigned)(M / 128);

    // x -> fp16
    split_x_kernel<<<(unsigned)((M * 16 + 255) / 256), 256>>>(x, M * 16);
    // L1: P1 = x @ W1 [M,1024];  h1 = relu(Mix.P1 + b1)
    gemm_tc_kernel<<<dim3(8, gm), 256, SMEM_BYTES>>>(hf, OW1, Pf, 64, 1024);
    gcn_post_kernel<<<(unsigned)(((long long)B * 256 + 255) / 256), 256>>>(
        b1, B, 1024);
    // L2: P2 = h1 @ [Wl2|Wr2] [M,1024];  h2 = sage_post(P2) [M,512]
    gemm_tc_kernel<<<dim3(8, gm), 256, SMEM_BYTES>>>(hf, OW2, Pf, 1024, 1024);
    sage_post_kernel<<<B, 128>>>(bl2, 512);
    // L3: P3 = h2 @ [Wl3|Wr3] [M,512];  h3 [M,256]
    gemm_tc_kernel<<<dim3(4, gm), 256, SMEM_BYTES>>>(hf, OW3, Pf, 512, 512);
    sage_post_kernel<<<B, 64>>>(bl3, 256);
    // L4: P4 = h3 @ [Wl4|Wr4] [M,512];  h4 [M,256]
    gemm_tc_kernel<<<dim3(4, gm), 256, SMEM_BYTES>>>(hf, OW4, Pf, 256, 512);
    sage_post_kernel<<<B, 64>>>(bl4, 256);
    // FC + softmax
    fc_softmax_kernel<<<(unsigned)((B * 32 + 255) / 256), 256>>>(
        Wfc, bfc, (float*)d_out, B);
}

// round 9
// speedup vs baseline: 7.1846x; 1.0689x over previous
#include <cuda_runtime.h>
#include <cuda_fp16.h>
#include <math.h>
#include <stdint.h>

// ===========================================================================
// GNN over fixed 4-node graph, B=32768 (M = 4B = 131072 rows).
// GEMMs: single mma.sync fp16 -> fp32 accum. 3-stage cp.async pipeline,
// smem-staged coalesced epilogue. GCN post (4x4 mix+bias+relu) fused into
// the L1 GEMM epilogue. SAGE mixing+norm in separate light post-passes.
// ===========================================================================

#define MAXB 32768
#define PADK 72                 // 64 + 8 pad (fp16) -> conflict-free ldmatrix
#define TILE_B (128 * PADK * 2) // 18432 bytes per 128x64 fp16 tile
#define STAGE_B (2 * TILE_B)    // A, W
#define STAGES 3
#define SMEM_BYTES (STAGES * STAGE_B)   // 110592
#define PADE 136                // epilogue staging stride (fp16 units)

__device__ float g_A[16];   // GCN normalized adjacency (4x4)
__device__ float g_M[16];   // SAGE mean-aggregation matrix (4x4)
__device__ __align__(16) __half g_Pf[(size_t)MAXB * 4 * 1024];    // fp16 GEMM out / x
__device__ __align__(16) __half g_hf[(size_t)MAXB * 4 * 1024];    // fp16 acts
__device__ __align__(16) __half g_wt[1507328];                    // fp16 weights

// ---------------------------------------------------------------------------
__device__ __forceinline__ uint32_t smem_u32(const void* p) {
    uint32_t a;
    asm("{ .reg .u64 t; cvta.to.shared.u64 t, %1; cvt.u32.u64 %0, t; }"
        : "=r"(a) : "l"(p));
    return a;
}
__device__ __forceinline__ void ldsm_x4(uint32_t (&r)[4], uint32_t addr) {
    asm volatile("ldmatrix.sync.aligned.m8n8.x4.shared.b16 {%0,%1,%2,%3}, [%4];"
                 : "=r"(r[0]), "=r"(r[1]), "=r"(r[2]), "=r"(r[3]) : "r"(addr));
}
__device__ __forceinline__ void ldsm_x2(uint32_t (&r)[2], uint32_t addr) {
    asm volatile("ldmatrix.sync.aligned.m8n8.x2.shared.b16 {%0,%1}, [%2];"
                 : "=r"(r[0]), "=r"(r[1]) : "r"(addr));
}
__device__ __forceinline__ void mma_f16(float (&d)[4], const uint32_t (&a)[4],
                                        const uint32_t (&b)[2]) {
    asm volatile(
        "mma.sync.aligned.m16n8k16.row.col.f32.f16.f16.f32 "
        "{%0,%1,%2,%3}, {%4,%5,%6,%7}, {%8,%9}, {%0,%1,%2,%3};"
        : "+f"(d[0]), "+f"(d[1]), "+f"(d[2]), "+f"(d[3])
        : "r"(a[0]), "r"(a[1]), "r"(a[2]), "r"(a[3]), "r"(b[0]), "r"(b[1]));
}
__device__ __forceinline__ void cp_async16(uint32_t dst, const void* src) {
    asm volatile("cp.async.cg.shared.global [%0], [%1], 16;"
                 :: "r"(dst), "l"(src));
}
#define CP_COMMIT() asm volatile("cp.async.commit_group;" ::: "memory")
#define CP_WAIT1()  asm volatile("cp.async.wait_group 1;" ::: "memory")

__device__ __forceinline__ uint32_t h2pack(float a, float b) {
    __half2 h = __floats2half2_rn(a, b);
    return *(uint32_t*)&h;
}
__device__ __forceinline__ void store_h4(__half* H, size_t e, float4 v) {
    *(uint2*)(H + e) = make_uint2(h2pack(v.x, v.y), h2pack(v.z, v.w));
}
__device__ __forceinline__ float4 load_h4(const __half* H, size_t e) {
    uint2 u = *(const uint2*)(H + e);
    __half2 p0 = *(__half2*)&u.x, p1 = *(__half2*)&u.y;
    float2 a = __half22float2(p0), b = __half22float2(p1);
    return make_float4(a.x, a.y, b.x, b.y);
}

// ---------------------------------------------------------------------------
// Build 4x4 mixing matrices from edge_index (dtype-adaptive int32/int64).
// ---------------------------------------------------------------------------
__global__ void build_graph_kernel(const void* __restrict__ ei_raw, int E)
{
    if (threadIdx.x != 0 || blockIdx.x != 0) return;
    const long long* e64 = (const long long*)ei_raw;
    const int*       e32 = (const int*)ei_raw;
    bool is64 = true;
    for (int e = 0; e < E; ++e) {
        long long v = e64[e];
        if (v < 0 || v >= 4) { is64 = false; break; }
    }
    int src[64], dst[64];
    for (int e = 0; e < E; ++e) {
        if (is64) { src[e] = (int)e64[e]; dst[e] = (int)e64[E + e]; }
        else      { src[e] = e32[e];      dst[e] = e32[E + e]; }
    }
    float degG[4] = {1.f, 1.f, 1.f, 1.f};
    float cntS[4] = {0.f, 0.f, 0.f, 0.f};
    for (int e = 0; e < E; ++e) { degG[dst[e]] += 1.f; cntS[dst[e]] += 1.f; }
    float dinv[4];
    #pragma unroll
    for (int n = 0; n < 4; ++n) dinv[n] = rsqrtf(degG[n]);
    float A[16], M[16];
    #pragma unroll
    for (int i = 0; i < 16; ++i) { A[i] = 0.f; M[i] = 0.f; }
    for (int e = 0; e < E; ++e) {
        int s = src[e], d = dst[e];
        A[d * 4 + s] += dinv[s] * dinv[d];
        M[d * 4 + s] += 1.f / fmaxf(cntS[d], 1.f);
    }
    #pragma unroll
    for (int n = 0; n < 4; ++n) A[n * 4 + n] += dinv[n] * dinv[n];
    #pragma unroll
    for (int i = 0; i < 16; ++i) { g_A[i] = A[i]; g_M[i] = M[i]; }
}

// ---------------------------------------------------------------------------
// Weight prep: fp32 W[K0,N] (row-major) -> fp16 stored [N][K0].
// ---------------------------------------------------------------------------
__global__ void prep_w_kernel(const float* __restrict__ W, int K0, int N,
                              size_t dst_off)
{
    long long idx = (long long)blockIdx.x * 256 + threadIdx.x;
    if (idx >= (long long)K0 * N) return;
    int k = (int)(idx / N), n = (int)(idx % N);
    g_wt[dst_off + (size_t)n * K0 + k] = __float2half_rn(W[idx]);
}

// ---------------------------------------------------------------------------
// Convert fp32 X to fp16 into g_Pf (input of L1 GEMM).
// ---------------------------------------------------------------------------
__global__ void split_x_kernel(const float* __restrict__ X, long long n4)
{
    long long i = (long long)blockIdx.x * 256 + threadIdx.x;
    if (i >= n4) return;
    float4 v = ((const float4*)X)[i];
    store_h4(g_Pf, (size_t)i * 4, v);
}

// ---------------------------------------------------------------------------
// fp16 GEMM: out[M,Ntot] = A[M,K0] @ W[K0,Ntot].
// post=0: store fp16 P (coalesced, via smem staging).
// post=1: GCN epilogue — y = relu(Mix4x4 . P + bias), store fp16 h.
// grid = (Ntot/128, M/128); 256 threads (8 warps 2x4); warp tile 64x32.
// 3-stage cp.async pipeline, wait_group 1, one __syncthreads per k-chunk.
// ---------------------------------------------------------------------------
__global__ __launch_bounds__(256, 2)
void gemm_tc_kernel(const __half* __restrict__ Ain, size_t w_off,
                    __half* __restrict__ Out, const float* __restrict__ bias,
                    int K0, int Ntot, int post)
{
    extern __shared__ char smem[];
    const uint32_t sbase = smem_u32(smem);
    const int tid = threadIdx.x, wid = tid >> 5, lid = tid & 31;
    const int by = blockIdx.x, bm = blockIdx.y;
    const int warp_m = wid & 1, warp_n = wid >> 1;
    const int m_base = warp_m * 64, n_base = warp_n * 32;

    float acc[4][4][4];
    #pragma unroll
    for (int mt = 0; mt < 4; ++mt)
        #pragma unroll
        for (int nt = 0; nt < 4; ++nt)
            #pragma unroll
            for (int i = 0; i < 4; ++i) acc[mt][nt][i] = 0.f;

    const int a_r  = lid & 15;
    const int a_ko = (lid >> 4) << 3;
    const int b_r  = lid & 7;
    const int b_ko = (lid & 8);

    const int KC = K0 >> 6;
    const __half* Ab = Ain + (size_t)bm * 128 * K0;
    const __half* Wb = g_wt + w_off + (size_t)by * 128 * K0;

    auto prefetch = [&](int kc) {
        uint32_t sb = sbase + (kc % STAGES) * STAGE_B;
        #pragma unroll
        for (int i = 0; i < 4; ++i) {
            int c = tid + i * 256, r = c >> 3, q = c & 7;
            uint32_t so = (uint32_t)(r * PADK + q * 8) * 2;
            size_t go = (size_t)r * K0 + (size_t)kc * 64 + q * 8;
            cp_async16(sb + so,          Ab + go);
            cp_async16(sb + TILE_B + so, Wb + go);
        }
        CP_COMMIT();
    };

    prefetch(0);
    if (KC > 1) prefetch(1); else CP_COMMIT();

    for (int kc = 0; kc < KC; ++kc) {
        CP_WAIT1();               // group kc complete (kc+1 may be in flight)
        __syncthreads();          // visible to all; stage kc+2 free to reuse
        if (kc + 2 < KC) prefetch(kc + 2); else CP_COMMIT();

        const uint32_t sb = sbase + (kc % STAGES) * STAGE_B;
        #pragma unroll
        for (int ks = 0; ks < 4; ++ks) {
            const int kof = ks * 16;
            uint32_t bh[4][2];
            #pragma unroll
            for (int nt = 0; nt < 4; ++nt) {
                uint32_t boff = (uint32_t)((n_base + nt * 8 + b_r) * PADK
                                           + kof + b_ko) * 2;
                ldsm_x2(bh[nt], sb + TILE_B + boff);
            }
            #pragma unroll
            for (int mt = 0; mt < 4; ++mt) {
                uint32_t aoff = (uint32_t)((m_base + mt * 16 + a_r) * PADK
                                           + kof + a_ko) * 2;
                uint32_t ah[4];
                ldsm_x4(ah, sb + aoff);
                #pragma unroll
                for (int nt = 0; nt < 4; ++nt)
                    mma_f16(acc[mt][nt], ah, bh[nt]);
            }
        }
    }

    // ---- epilogue: stage fp16 tile [128][PADE] in smem, then coalesce ----
    __syncthreads();              // done with pipeline smem
    {
        const int rq = lid >> 2, cq = (lid & 3) * 2;
        #pragma unroll
        for (int mt = 0; mt < 4; ++mt) {
            #pragma unroll
            for (int nt = 0; nt < 4; ++nt) {
                int col = n_base + nt * 8 + cq;
                int r0 = m_base + mt * 16 + rq;
                *(uint32_t*)(smem + (r0 * PADE + col) * 2) =
                    h2pack(acc[mt][nt][0], acc[mt][nt][1]);
                *(uint32_t*)(smem + ((r0 + 8) * PADE + col) * 2) =
                    h2pack(acc[mt][nt][2], acc[mt][nt][3]);
            }
        }
    }
    __syncthreads();

    if (post == 0) {
        // coalesced 128-bit stores: 16 lanes cover one 128-col row
        const int rbase = tid >> 4, cg = (tid & 15) * 8;
        #pragma unroll
        for (int it = 0; it < 8; ++it) {
            int row = rbase + it * 16;
            uint4 v = *(uint4*)(smem + (row * PADE + cg) * 2);
            *(uint4*)(Out + ((size_t)bm * 128 + row) * Ntot
                          + (size_t)by * 128 + cg) = v;
        }
    } else {
        // GCN: y[n] = relu( sum_m A[n,m] * P[b*4+m] + bias ); Ntot == 1024
        float mat[16];
        #pragma unroll
        for (int i = 0; i < 16; ++i) mat[i] = g_A[i];
        #pragma unroll
        for (int it = 0; it < 2; ++it) {
            int item = it * 256 + tid;        // 0..511
            int b = item >> 4, ch = item & 15;
            int colg = by * 128 + ch * 8;
            float4 bv0 = *(const float4*)(bias + colg);
            float4 bv1 = *(const float4*)(bias + colg + 4);
            float bb[8] = {bv0.x, bv0.y, bv0.z, bv0.w, bv1.x, bv1.y, bv1.z, bv1.w};
            float v[4][8];
            #pragma unroll
            for (int m = 0; m < 4; ++m) {
                uint4 u = *(uint4*)(smem + ((b * 4 + m) * PADE + ch * 8) * 2);
                uint32_t* up = (uint32_t*)&u;
                #pragma unroll
                for (int q = 0; q < 4; ++q) {
                    float2 f = __half22float2(*(__half2*)&up[q]);
                    v[m][q * 2] = f.x; v[m][q * 2 + 1] = f.y;
                }
            }
            #pragma unroll
            for (int n = 0; n < 4; ++n) {
                uint32_t o[4];
                #pragma unroll
                for (int q = 0; q < 4; ++q) {
                    float y0 = fmaxf(mat[n*4+0]*v[0][q*2]   + mat[n*4+1]*v[1][q*2]
                                   + mat[n*4+2]*v[2][q*2]   + mat[n*4+3]*v[3][q*2]
                                   + bb[q*2], 0.f);
                    float y1 = fmaxf(mat[n*4+0]*v[0][q*2+1] + mat[n*4+1]*v[1][q*2+1]
                                   + mat[n*4+2]*v[2][q*2+1] + mat[n*4+3]*v[3][q*2+1]
                                   + bb[q*2+1], 0.f);
                    o[q] = h2pack(y0, y1);
                }
                size_t row = (size_t)bm * 128 + b * 4 + n;
                *(uint4*)(Out + row * 1024 + colg) = *(uint4*)o;
            }
        }
    }
}

// ---------------------------------------------------------------------------
// SAGE post: P[M, 2N] = [Pl | Pr], fp16.  h[b,n,:] =
//   relu( l2norm( Mix.Pl[b,:,:] (row n) + Pr[b,n,:] + bias ) ), fp16 out.
// One block per batch; blockDim = N/4.
// ---------------------------------------------------------------------------
__global__ void sage_post_kernel(const float* __restrict__ bias, int N)
{
    __shared__ float red[4][4];
    const int b = blockIdx.x, tid = threadIdx.x;
    const int wid = tid >> 5, lane = tid & 31;
    const int nw = blockDim.x >> 5;
    float mat[16];
    #pragma unroll
    for (int i = 0; i < 16; ++i) mat[i] = g_M[i];

    const size_t Pb = (size_t)b * 4 * (2 * N);
    const int f = tid * 4;
    float4 pl[4];
    #pragma unroll
    for (int m = 0; m < 4; ++m)
        pl[m] = load_h4(g_Pf, Pb + (size_t)m * 2 * N + f);
    float4 bv = *(const float4*)(bias + f);

    float4 y[4];
    float ss[4];
    #pragma unroll
    for (int n = 0; n < 4; ++n) {
        float4 pr = load_h4(g_Pf, Pb + (size_t)n * 2 * N + N + f);
        float4 r;
        r.x = mat[n*4+0]*pl[0].x + mat[n*4+1]*pl[1].x + mat[n*4+2]*pl[2].x + mat[n*4+3]*pl[3].x + pr.x + bv.x;
        r.y = mat[n*4+0]*pl[0].y + mat[n*4+1]*pl[1].y + mat[n*4+2]*pl[2].y + mat[n*4+3]*pl[3].y + pr.y + bv.y;
        r.z = mat[n*4+0]*pl[0].z + mat[n*4+1]*pl[1].z + mat[n*4+2]*pl[2].z + mat[n*4+3]*pl[3].z + pr.z + bv.z;
        r.w = mat[n*4+0]*pl[0].w + mat[n*4+1]*pl[1].w + mat[n*4+2]*pl[2].w + mat[n*4+3]*pl[3].w + pr.w + bv.w;
        y[n] = r;
        ss[n] = r.x * r.x + r.y * r.y + r.z * r.z + r.w * r.w;
    }
    #pragma unroll
    for (int n = 0; n < 4; ++n)
        #pragma unroll
        for (int off = 16; off > 0; off >>= 1)
            ss[n] += __shfl_xor_sync(0xffffffffu, ss[n], off);
    if (lane == 0) {
        #pragma unroll
        for (int n = 0; n < 4; ++n) red[n][wid] = ss[n];
    }
    __syncthreads();
    float inv[4];
    #pragma unroll
    for (int n = 0; n < 4; ++n) {
        float t = 0.f;
        for (int w = 0; w < nw; ++w) t += red[n][w];
        inv[n] = 1.f / fmaxf(sqrtf(t), 1e-12f);
    }
    #pragma unroll
    for (int n = 0; n < 4; ++n) {
        float4 o;
        o.x = fmaxf(y[n].x * inv[n], 0.f);
        o.y = fmaxf(y[n].y * inv[n], 0.f);
        o.z = fmaxf(y[n].z * inv[n], 0.f);
        o.w = fmaxf(y[n].w * inv[n], 0.f);
        store_h4(g_hf, (size_t)(b * 4 + n) * N + f, o);
    }
}

// ---------------------------------------------------------------------------
// FC [B,1024] @ Wfc[1024,10] + bfc, softmax. One warp per batch row.
// ---------------------------------------------------------------------------
__global__ void fc_softmax_kernel(const float* __restrict__ Wfc,
                                  const float* __restrict__ bfc,
                                  float* __restrict__ out, int B)
{
    long long warp = ((long long)blockIdx.x * blockDim.x + threadIdx.x) >> 5;
    int lane = threadIdx.x & 31;
    if (warp >= B) return;
    const size_t base = (size_t)warp * 1024;
    float acc[10];
    #pragma unroll
    for (int o = 0; o < 10; ++o) acc[o] = 0.f;
    for (int k = lane; k < 1024; k += 32) {
        float hv = __half2float(g_hf[base + k]);
        const float* w = Wfc + (size_t)k * 10;
        #pragma unroll
        for (int o = 0; o < 10; ++o) acc[o] += hv * w[o];
    }
    #pragma unroll
    for (int o = 0; o < 10; ++o)
        #pragma unroll
        for (int off = 16; off > 0; off >>= 1)
            acc[o] += __shfl_xor_sync(0xffffffffu, acc[o], off);
    if (lane == 0) {
        float logit[10], m = -1e30f;
        #pragma unroll
        for (int o = 0; o < 10; ++o) {
            logit[o] = acc[o] + bfc[o];
            m = fmaxf(m, logit[o]);
        }
        float s = 0.f;
        #pragma unroll
        for (int o = 0; o < 10; ++o) { logit[o] = expf(logit[o] - m); s += logit[o]; }
        float invs = 1.f / s;
        float* orow = out + (size_t)warp * 10;
        #pragma unroll
        for (int o = 0; o < 10; ++o) orow[o] = logit[o] * invs;
    }
}

// ---------------------------------------------------------------------------
extern "C" void kernel_launch(void* const* d_in, const int* in_sizes, int n_in,
                              void* d_out, int out_size)
{
    const float* x   = (const float*)d_in[0];
    const void*  ei  = d_in[1];
    const float* W1  = (const float*)d_in[2];
    const float* b1  = (const float*)d_in[3];
    const float* Wl2 = (const float*)d_in[4];
    const float* bl2 = (const float*)d_in[5];
    const float* Wr2 = (const float*)d_in[6];
    const float* Wl3 = (const float*)d_in[7];
    const float* bl3 = (const float*)d_in[8];
    const float* Wr3 = (const float*)d_in[9];
    const float* Wl4 = (const float*)d_in[10];
    const float* bl4 = (const float*)d_in[11];
    const float* Wr4 = (const float*)d_in[12];
    const float* Wfc = (const float*)d_in[13];
    const float* bfc = (const float*)d_in[14];

    const int B = in_sizes[0] / (4 * 64);
    const int E = in_sizes[1] / 2;
    const long long M = (long long)B * 4;

    __half *Pf, *hf;
    cudaGetSymbolAddress((void**)&Pf, g_Pf);
    cudaGetSymbolAddress((void**)&hf, g_hf);

    cudaFuncSetAttribute(gemm_tc_kernel,
                         cudaFuncAttributeMaxDynamicSharedMemorySize, SMEM_BYTES);

    build_graph_kernel<<<1, 32>>>(ei, E);

    // weight prep: N-concat layout [Ntot][K0], offsets in fp16 elements
    const size_t OW1 = 0;                       // [1024][64]
    const size_t OW2 = 65536;                   // [1024][1024] = [Wl2|Wr2]
    const size_t OW3 = OW2 + 1048576;           // [512][512]  = [Wl3|Wr3]
    const size_t OW4 = OW3 + 262144;            // [512][256]  = [Wl4|Wr4]
    prep_w_kernel<<<(64   * 1024 + 255) / 256, 256>>>(W1,  64,   1024, OW1);
    prep_w_kernel<<<(1024 * 512  + 255) / 256, 256>>>(Wl2, 1024, 512,  OW2);
    prep_w_kernel<<<(1024 * 512  + 255) / 256, 256>>>(Wr2, 1024, 512,  OW2 + (size_t)512 * 1024);
    prep_w_kernel<<<(512  * 256  + 255) / 256, 256>>>(Wl3, 512,  256,  OW3);
    prep_w_kernel<<<(512  * 256  + 255) / 256, 256>>>(Wr3, 512,  256,  OW3 + (size_t)256 * 512);
    prep_w_kernel<<<(256  * 256  + 255) / 256, 256>>>(Wl4, 256,  256,  OW4);
    prep_w_kernel<<<(256  * 256  + 255) / 256, 256>>>(Wr4, 256,  256,  OW4 + (size_t)256 * 256);

    const unsigned gm = (unsigned)(M / 128);

    // x -> fp16 (into g_Pf, the L1 GEMM input)
    split_x_kernel<<<(unsigned)((M * 16 + 255) / 256), 256>>>(x, M * 16);
    // L1: h1 = relu(Mix.(x@W1) + b1) — GCN post fused into epilogue
    gemm_tc_kernel<<<dim3(8, gm), 256, SMEM_BYTES>>>(Pf, OW1, hf, b1, 64, 1024, 1);
    // L2: P2 = h1 @ [Wl2|Wr2] [M,1024];  h2 = sage_post(P2) [M,512]
    gemm_tc_kernel<<<dim3(8, gm), 256, SMEM_BYTES>>>(hf, OW2, Pf, b1, 1024, 1024, 0);
    sage_post_kernel<<<B, 128>>>(bl2, 512);
    // L3: P3 = h2 @ [Wl3|Wr3] [M,512];  h3 [M,256]
    gemm_tc_kernel<<<dim3(4, gm), 256, SMEM_BYTES>>>(hf, OW3, Pf, b1, 512, 512, 0);
    sage_post_kernel<<<B, 64>>>(bl3, 256);
    // L4: P4 = h3 @ [Wl4|Wr4] [M,512];  h4 [M,256]
    gemm_tc_kernel<<<dim3(4, gm), 256, SMEM_BYTES>>>(hf, OW4, Pf, b1, 256, 512, 0);
    sage_post_kernel<<<B, 64>>>(bl4, 256);
    // FC + softmax
    fc_softmax_kernel<<<(unsigned)((B * 32 + 255) / 256), 256>>>(
        Wfc, bfc, (float*)d_out, B);
}